// round 7
// baseline (speedup 1.0000x reference)
#include <cuda_runtime.h>
#include <math.h>

#define NB 32      // batch
#define NT 400     // timesteps
#define NU 400     // LSTM units
#define NKG 10     // attention gaussians
#define NC 73      // alphabet
#define NUC 50     // char positions
#define NO 121     // MDN outputs
#define H4 1600    // 4*NU
#define NCTA 150
#define NTH 512
#define NWP 16

typedef unsigned long long ull;
#define ull2 ulonglong2

// ---------------- packed weights (gate-interleaved float4 per (u,k)) ----------------
__device__ float4 d_P0  [NU*476];  // layer1: [x(3), w(73), h1(400)]
__device__ float4 d_P1r [NU*403];  // layer2 recurrent: [x(3), h2(400)]
__device__ float4 d_P1h [NU*400];  // layer2 h1 part of Wx1
__device__ float4 d_P1w [NU*73];   // layer2 w part of Wx1
__device__ float4 d_P2r [NU*403];  // layer3 recurrent: [x(3), h3(400)]
__device__ float4 d_P2wh[NU*473];  // layer3 [w(73), h2(400)] part of Wx2

// ---------------- state, transposed [u][b] ----------------
__device__ float d_h1a[NU*NB];
__device__ float d_h1b[NU*NB];
__device__ float d_h2 [NU*NB];
__device__ float d_h3 [NU*NB];
__device__ float d_Z2p[NU*4*NB];
__device__ float d_R3p[NU*4*NB];
__device__ float d_wT [NC*NB];
__device__ float d_h3all[NT*NU*NB];

// ---------------- sync state ----------------
__device__ unsigned d_arr[160];     // per-CTA barrier arrival slots
__device__ unsigned d_release;      // barrier release flag
__device__ unsigned d_flags[64];    // [0..49]: h2 ready per CTA; [50..53]: w ready per att CTA

// =====================================================================
// pack kernel: gate-interleave weights + zero all state/sync
// =====================================================================
__global__ void pack_kernel(const float* __restrict__ Wx0, const float* __restrict__ Wh0,
                            const float* __restrict__ Wx1, const float* __restrict__ Wh1,
                            const float* __restrict__ Wx2, const float* __restrict__ Wh2)
{
    int idx = blockIdx.x * blockDim.x + threadIdx.x;
    int str = gridDim.x * blockDim.x;

    for (int e = idx; e < 160; e += str) d_arr[e] = 0u;
    for (int e = idx; e < 64; e += str) d_flags[e] = 0u;
    if (idx == 0) d_release = 0u;
    for (int e = idx; e < NU*NB; e += str) {
        d_h1a[e] = 0.f; d_h1b[e] = 0.f; d_h2[e] = 0.f; d_h3[e] = 0.f;
    }
    for (int e = idx; e < NC*NB; e += str) d_wT[e] = 0.f;

    for (int e = idx; e < NU*476; e += str) {
        int u = e / 476, k = e - u*476;
        const float* s = (k < 76) ? (Wx0 + k*H4) : (Wh0 + (k-76)*H4);
        d_P0[e] = make_float4(s[u], s[NU+u], s[2*NU+u], s[3*NU+u]);
    }
    for (int e = idx; e < NU*403; e += str) {
        int u = e / 403, k = e - u*403;
        const float* s = (k < 3) ? (Wx1 + k*H4) : (Wh1 + (k-3)*H4);
        d_P1r[e] = make_float4(s[u], s[NU+u], s[2*NU+u], s[3*NU+u]);
    }
    for (int e = idx; e < NU*400; e += str) {
        int u = e / 400, k = e - u*400;
        const float* s = Wx1 + (76+k)*H4;
        d_P1h[e] = make_float4(s[u], s[NU+u], s[2*NU+u], s[3*NU+u]);
    }
    for (int e = idx; e < NU*73; e += str) {
        int u = e / 73, k = e - u*73;
        const float* s = Wx1 + (3+k)*H4;
        d_P1w[e] = make_float4(s[u], s[NU+u], s[2*NU+u], s[3*NU+u]);
    }
    for (int e = idx; e < NU*403; e += str) {
        int u = e / 403, k = e - u*403;
        const float* s = (k < 3) ? (Wx2 + k*H4) : (Wh2 + (k-3)*H4);
        d_P2r[e] = make_float4(s[u], s[NU+u], s[2*NU+u], s[3*NU+u]);
    }
    for (int e = idx; e < NU*473; e += str) {
        int u = e / 473, k = e - u*473;
        const float* s = Wx2 + (3+k)*H4;
        d_P2wh[e] = make_float4(s[u], s[NU+u], s[2*NU+u], s[3*NU+u]);
    }
}

// =====================================================================
// helpers
// =====================================================================
__device__ __forceinline__ float sigf(float x) { return 1.f / (1.f + expf(-x)); }

__device__ __forceinline__ ull pk2(float v) {
    ull r; asm("mov.b64 %0, {%1, %1};" : "=l"(r) : "f"(v)); return r;
}
__device__ __forceinline__ ull pk(float lo, float hi) {
    ull r; asm("mov.b64 %0, {%1, %2};" : "=l"(r) : "f"(lo), "f"(hi)); return r;
}
__device__ __forceinline__ void upk(ull v, float& lo, float& hi) {
    asm("mov.b64 {%0, %1}, %2;" : "=f"(lo), "=f"(hi) : "l"(v));
}
__device__ __forceinline__ void fma2(ull& d, ull a, ull b) {
    asm("fma.rn.f32x2 %0, %1, %2, %0;" : "+l"(d) : "l"(a), "l"(b));
}

__device__ __forceinline__ void st_rel(unsigned* p, unsigned v) {
    asm volatile("{ .reg .u64 a; cvta.to.global.u64 a, %0; st.release.gpu.global.u32 [a], %1; }"
                 :: "l"(p), "r"(v) : "memory");
}
__device__ __forceinline__ unsigned ld_acq(const unsigned* p) {
    unsigned v;
    asm volatile("{ .reg .u64 a; cvta.to.global.u64 a, %1; ld.acquire.gpu.global.u32 %0, [a]; }"
                 : "=r"(v) : "l"(p) : "memory");
    return v;
}

// barrier: distributed arrival (release stores), CTA0 warp0 acquire-polls all
// slots + release-stores flag. No atomics serialization, no fence/IVALL anywhere.
__device__ __forceinline__ void gsync(unsigned r, int cta)
{
    __syncthreads();
    if (cta == 0) {
        if (threadIdx.x < 32) {
            int lane = threadIdx.x;
            bool done;
            do {
                unsigned mn = 0xffffffffu;
#pragma unroll
                for (int i = 0; i < 5; i++) {
                    int s = lane + i*32;
                    unsigned v = r;
                    if (s > 0 && s < NCTA) v = ld_acq(d_arr + s);
                    mn = min(mn, v);
                }
                done = __all_sync(0xffffffffu, mn >= r);
            } while (!done);
            if (lane == 0) st_rel(&d_release, r);
        }
    } else {
        if (threadIdx.x == 0) {
            st_rel(d_arr + cta, r);
            while (ld_acq(&d_release) < r) { }
        }
    }
    __syncthreads();
}

// bulk copy global(L2,.cg) -> shared
__device__ __forceinline__ void copy4(float* dst, const float* src, int nfl)
{
    const float4* s = (const float4*)src;
    float4* d = (float4*)dst;
    int n4 = nfl >> 2;
    for (int i = threadIdx.x; i < n4; i += NTH) d[i] = __ldcg(s + i);
}

__device__ __forceinline__ void accseg(ull& a01, ull& a23,
                                       const ull2* __restrict__ P,
                                       const float* __restrict__ vs, int K, int b)
{
#pragma unroll 4
    for (int k = 0; k < K; k++) {
        ull hh = pk2(vs[k*NB + b]);
        ull2 w = __ldg(P + k);
        fma2(a01, w.x, hh);
        fma2(a23, w.y, hh);
    }
}

__device__ __forceinline__ void accx(ull& a01, ull& a23, const ull2* __restrict__ P,
                                     float x0, float x1, float x2)
{
    ull2 w0 = __ldg(P+0), w1 = __ldg(P+1), w2 = __ldg(P+2);
    ull X0 = pk2(x0), X1 = pk2(x1), X2 = pk2(x2);
    fma2(a01, w0.x, X0); fma2(a23, w0.y, X0);
    fma2(a01, w1.x, X1); fma2(a23, w1.y, X1);
    fma2(a01, w2.x, X2); fma2(a23, w2.y, X2);
}

// =====================================================================
// persistent RNN kernel: 150 CTAs x 512 threads
// =====================================================================
__global__ void __launch_bounds__(NTH, 1)
rnn_kernel(const float* __restrict__ strokes,
           const int*   __restrict__ chars,
           const int*   __restrict__ lens,
           const float* __restrict__ b0, const float* __restrict__ p0,
           const float* __restrict__ b1, const float* __restrict__ p1,
           const float* __restrict__ b2, const float* __restrict__ p2,
           const float* __restrict__ Watt, const float* __restrict__ batt,
           const float* __restrict__ Wmdn, const float* __restrict__ bmdn,
           float* __restrict__ out)
{
    extern __shared__ float smem[];
    float* s_h   = smem;            // 12800: staged h-vector [k][b]
    float* s_wc  = smem + 12800;    // 2336: staged w-vector [k][b]
    float* s_red = smem + 15136;    // 16*128: K-split partial reduction
    float* s_att = smem + 17184;    // 8*76: attention scatter scratch

    const int cta  = blockIdx.x;
    const int tid  = threadIdx.x;
    const int lane = tid & 31;
    const int wib  = tid >> 5;
    const int b    = lane;
    const unsigned FULL = 0xffffffffu;

    // register-resident recurrent cell state (stable warp<->unit maps)
    float c1reg = 0.f;   // CTAs 0-49,  wib<8, unit = cta*8+wib
    float c2reg = 0.f;   // CTAs 0-49,  wib<8, same unit
    float c3reg = 0.f;   // CTAs 0-99,  wib<4, unit = cta*4+wib
    float kapreg = 0.f;  // CTAs 100-103, wib even, lane<10

    for (int t = 0; t < NT; t++) {
        const float* h1prev = (t & 1) ? d_h1b : d_h1a;
        float*       h1cur  = (t & 1) ? d_h1a : d_h1b;

        // ======== stage 1: z1+LSTM1 (0-49) | R2 (50-99) | R3 (100-149), K-split x2 ========
        {
            const float* xp = strokes + (b*NT + t)*3;
            int j = wib >> 1, half = wib & 1;
            if (cta < 50) {
                copy4(s_h,  h1prev, NU*NB);
                copy4(s_wc, d_wT,   NC*NB);
                __syncthreads();
                int u = cta*8 + j;
                ull a01 = 0ull, a23 = 0ull;
                const ull2* P = (const ull2*)(d_P0 + u*476);
                if (half == 0) {
                    accx(a01, a23, P, __ldg(xp), __ldg(xp+1), __ldg(xp+2));
                    accseg(a01, a23, P+3,  s_wc, NC, b);
                    accseg(a01, a23, P+76, s_h, 162, b);
                } else {
                    accseg(a01, a23, P+238, s_h + 162*NB, 238, b);
                }
                float g0,g1,g2,g3; upk(a01,g0,g1); upk(a23,g2,g3);
                float* rp = s_red + wib*128 + b;
                rp[0]=g0; rp[32]=g1; rp[64]=g2; rp[96]=g3;
                __syncthreads();
                if (wib < 8) {
                    int uu = cta*8 + wib;
                    const float* r0 = s_red + (2*wib)*128 + b;
                    const float* r1 = s_red + (2*wib+1)*128 + b;
                    float zi = r0[0]  + r1[0]  + __ldg(b0+uu);
                    float zf = r0[32] + r1[32] + __ldg(b0+NU+uu);
                    float zg = r0[64] + r1[64] + __ldg(b0+2*NU+uu);
                    float zo = r0[96] + r1[96] + __ldg(b0+3*NU+uu);
                    float ig = sigf(zi + __ldg(p0+uu)      * c1reg);
                    float fg = sigf(zf + __ldg(p0+NU+uu)   * c1reg);
                    float cn = fg*c1reg + ig*tanhf(zg);
                    float og = sigf(zo + __ldg(p0+2*NU+uu) * cn);
                    c1reg = cn;
                    __stcg(&h1cur[uu*NB + b], og * tanhf(cn));
                }
            } else if (cta < 100) {
                copy4(s_h, d_h2, NU*NB);
                __syncthreads();
                int u = (cta-50)*8 + j;
                ull a01 = 0ull, a23 = 0ull;
                const ull2* P = (const ull2*)(d_P1r + u*403);
                if (half == 0) {
                    accx(a01, a23, P, __ldg(xp), __ldg(xp+1), __ldg(xp+2));
                    accseg(a01, a23, P+3, s_h, 200, b);
                } else {
                    accseg(a01, a23, P+203, s_h + 200*NB, 200, b);
                }
                float g0,g1,g2,g3; upk(a01,g0,g1); upk(a23,g2,g3);
                float* rp = s_red + wib*128 + b;
                rp[0]=g0; rp[32]=g1; rp[64]=g2; rp[96]=g3;
                __syncthreads();
                if (wib < 8) {
                    int uu = (cta-50)*8 + wib;
                    const float* r0 = s_red + (2*wib)*128 + b;
                    const float* r1 = s_red + (2*wib+1)*128 + b;
                    float* dp = d_Z2p + uu*128 + b;
                    __stcg(dp+0,  r0[0]  + r1[0]  + __ldg(b1+uu));
                    __stcg(dp+32, r0[32] + r1[32] + __ldg(b1+NU+uu));
                    __stcg(dp+64, r0[64] + r1[64] + __ldg(b1+2*NU+uu));
                    __stcg(dp+96, r0[96] + r1[96] + __ldg(b1+3*NU+uu));
                }
            } else {
                copy4(s_h, d_h3, NU*NB);
                __syncthreads();
                int u = (cta-100)*8 + j;
                ull a01 = 0ull, a23 = 0ull;
                const ull2* P = (const ull2*)(d_P2r + u*403);
                if (half == 0) {
                    accx(a01, a23, P, __ldg(xp), __ldg(xp+1), __ldg(xp+2));
                    accseg(a01, a23, P+3, s_h, 200, b);
                } else {
                    accseg(a01, a23, P+203, s_h + 200*NB, 200, b);
                }
                float g0,g1,g2,g3; upk(a01,g0,g1); upk(a23,g2,g3);
                float* rp = s_red + wib*128 + b;
                rp[0]=g0; rp[32]=g1; rp[64]=g2; rp[96]=g3;
                __syncthreads();
                if (wib < 8) {
                    int uu = (cta-100)*8 + wib;
                    const float* r0 = s_red + (2*wib)*128 + b;
                    const float* r1 = s_red + (2*wib+1)*128 + b;
                    float* dp = d_R3p + uu*128 + b;
                    __stcg(dp+0,  r0[0]  + r1[0]  + __ldg(b2+uu));
                    __stcg(dp+32, r0[32] + r1[32] + __ldg(b2+NU+uu));
                    __stcg(dp+64, r0[64] + r1[64] + __ldg(b2+2*NU+uu));
                    __stcg(dp+96, r0[96] + r1[96] + __ldg(b2+3*NU+uu));
                }
            }
        }
        gsync(2*t + 1, cta);

        // ======== stage 2/3 merged: Z2h (smem partials) + attention(w) -> z2+LSTM2 ========
        if (cta < 50) {
            copy4(s_h, h1cur, NU*NB);
            __syncthreads();
            {
                int j = wib >> 1, half = wib & 1;
                int u = cta*8 + j;
                ull a01 = 0ull, a23 = 0ull;
                accseg(a01, a23, (const ull2*)(d_P1h + u*400) + half*200,
                       s_h + half*200*NB, 200, b);
                float g0,g1,g2,g3; upk(a01,g0,g1); upk(a23,g2,g3);
                float* rp = s_red + wib*128 + b;
                rp[0]=g0; rp[32]=g1; rp[64]=g2; rp[96]=g3;
            }
            __syncthreads();
            if (tid < 32) {              // wait for attention w (4 producer flags)
                bool done;
                do {
                    unsigned v = (lane < 4) ? ld_acq(d_flags + 50 + lane) : FULL;
                    done = __all_sync(FULL, v >= (unsigned)(t+1));
                } while (!done);
            }
            __syncthreads();
            copy4(s_wc, d_wT, NC*NB);
            __syncthreads();
            if (wib < 8) {
                int uu = cta*8 + wib;
                int o4 = uu*128 + b;
                const float* r0 = s_red + (2*wib)*128 + b;
                const float* r1 = s_red + (2*wib+1)*128 + b;
                float z0 = __ldcg(d_Z2p+o4)    + r0[0]  + r1[0];
                float z1 = __ldcg(d_Z2p+o4+32) + r0[32] + r1[32];
                float z2 = __ldcg(d_Z2p+o4+64) + r0[64] + r1[64];
                float z3 = __ldcg(d_Z2p+o4+96) + r0[96] + r1[96];
                ull a01 = pk(z0,z1), a23 = pk(z2,z3);
                accseg(a01, a23, (const ull2*)(d_P1w + uu*73), s_wc, NC, b);
                float zi,zf,zg,zo; upk(a01,zi,zf); upk(a23,zg,zo);
                float ig = sigf(zi + __ldg(p1+uu)      * c2reg);
                float fg = sigf(zf + __ldg(p1+NU+uu)   * c2reg);
                float cn = fg*c2reg + ig*tanhf(zg);
                float og = sigf(zo + __ldg(p1+2*NU+uu) * cn);
                c2reg = cn;
                __stcg(&d_h2[uu*NB + b], og * tanhf(cn));
            }
            __syncthreads();
            if (tid == 0) st_rel(d_flags + cta, (unsigned)(t+1));   // h2 ready
        } else if (cta >= 100 && cta < 104) {
            // attention: 8 batches per CTA, 2-warp K-split GEMV
            copy4(s_h, h1cur, NU*NB);
            __syncthreads();
            int a = wib >> 1, half = wib & 1;
            int ab = (cta-100)*8 + a;
            float acc = 0.f;
            if (lane < 30) {
#pragma unroll 4
                for (int k = half*200; k < half*200 + 200; k++)
                    acc = fmaf(s_h[k*NB + ab], __ldg(Watt + k*30 + lane), acc);
            }
            s_red[wib*128 + lane] = acc;
            __syncthreads();
            if (half == 0) {
                float att = s_red[wib*128 + lane] + s_red[(wib+1)*128 + lane]
                          + ((lane < 30) ? __ldg(batt + lane) : 0.f);
                float ah = __shfl_sync(FULL, att, (lane < 10) ? lane      : 0);
                float bh = __shfl_sync(FULL, att, (lane < 10) ? lane + 10 : 10);
                float kh = __shfl_sync(FULL, att, (lane < 10) ? lane + 20 : 20);
                float alpha = 0.f, beta = 0.f;
                if (lane < 10) {
                    alpha = expf(ah);
                    beta  = expf(bh);
                    kapreg = kapreg + expf(kh);
                }
                float* sw = s_att + a*76;
                for (int c = lane; c < NC; c += 32) sw[c] = 0.f;
                __syncwarp();
                int lb = __ldg(lens + ab);
#pragma unroll
                for (int hh = 0; hh < 2; hh++) {
                    int uu = lane + hh*32;
                    float phi = 0.f;
#pragma unroll
                    for (int g = 0; g < NKG; g++) {
                        float ag = __shfl_sync(FULL, alpha,  g);
                        float bg = __shfl_sync(FULL, beta,   g);
                        float kg = __shfl_sync(FULL, kapreg, g);
                        float df = kg - (float)uu;
                        phi = fmaf(ag, expf(-bg*df*df), phi);
                    }
                    if (uu < NUC && uu < lb) {
                        int c = __ldg(chars + ab*NUC + uu);
                        atomicAdd(&sw[c], phi);
                    }
                }
                __syncwarp();
                for (int c = lane; c < NC; c += 32) __stcg(&d_wT[c*NB + ab], sw[c]);
            }
            __syncthreads();
            if (tid == 0) st_rel(d_flags + 50 + (cta-100), (unsigned)(t+1));  // w ready
        }

        // ======== stage 4: z3 = R3p + [w,h2]@P2wh (4-warp K-split) -> LSTM3 ========
        if (cta < 100) {
            if (tid < 32) {              // wait for all h2 (50) + w (4) flags
                bool done;
                do {
                    unsigned v0 = (lane < 54)      ? ld_acq(d_flags + lane)      : FULL;
                    unsigned v1 = (lane + 32 < 54) ? ld_acq(d_flags + lane + 32) : FULL;
                    done = __all_sync(FULL, min(v0, v1) >= (unsigned)(t+1));
                } while (!done);
            }
            __syncthreads();
            copy4(s_h,  d_h2, NU*NB);
            copy4(s_wc, d_wT, NC*NB);
            __syncthreads();
            {
                int j = wib >> 2, q = wib & 3;
                int u = cta*4 + j;
                ull a01 = 0ull, a23 = 0ull;
                const ull2* P = (const ull2*)(d_P2wh + u*473);
                if (q == 0) {
                    accseg(a01, a23, P,    s_wc, NC, b);
                    accseg(a01, a23, P+73, s_h, 46, b);
                } else if (q == 1) {
                    accseg(a01, a23, P+119, s_h + 46*NB, 118, b);
                } else if (q == 2) {
                    accseg(a01, a23, P+237, s_h + 164*NB, 118, b);
                } else {
                    accseg(a01, a23, P+355, s_h + 282*NB, 118, b);
                }
                float g0,g1,g2,g3; upk(a01,g0,g1); upk(a23,g2,g3);
                float* rp = s_red + wib*128 + b;
                rp[0]=g0; rp[32]=g1; rp[64]=g2; rp[96]=g3;
            }
            __syncthreads();
            if (wib < 4) {
                int uu = cta*4 + wib;
                int o4 = uu*128 + b;
                const float* r0 = s_red + (4*wib)*128 + b;
                const float* r1 = s_red + (4*wib+1)*128 + b;
                const float* r2 = s_red + (4*wib+2)*128 + b;
                const float* r3 = s_red + (4*wib+3)*128 + b;
                float zi = __ldcg(d_R3p+o4)    + r0[0]  + r1[0]  + r2[0]  + r3[0];
                float zf = __ldcg(d_R3p+o4+32) + r0[32] + r1[32] + r2[32] + r3[32];
                float zg = __ldcg(d_R3p+o4+64) + r0[64] + r1[64] + r2[64] + r3[64];
                float zo = __ldcg(d_R3p+o4+96) + r0[96] + r1[96] + r2[96] + r3[96];
                float ig = sigf(zi + __ldg(p2+uu)      * c3reg);
                float fg = sigf(zf + __ldg(p2+NU+uu)   * c3reg);
                float cn = fg*c3reg + ig*tanhf(zg);
                float og = sigf(zo + __ldg(p2+2*NU+uu) * cn);
                c3reg = cn;
                float hv = og * tanhf(cn);
                __stcg(&d_h3[uu*NB + b], hv);
                __stcg(&d_h3all[(t*NU + uu)*NB + b], hv);
            }
        }
        gsync(2*t + 2, cta);
    }

    // ================= MDN head =================
    const int gw = cta*NWP + wib;
    const int NW = NCTA*NWP;
    for (int task = gw; task < NB*NT; task += NW) {
        int bb = task / NT;
        int tt = task - bb*NT;
        const float* h3p = d_h3all + (tt*NU)*NB + bb;

        int j0 = lane, j1 = lane + 32, j2 = lane + 64, j3 = lane + 96;
        float a0 = __ldg(bmdn + j0);
        float a1 = __ldg(bmdn + j1);
        float a2 = __ldg(bmdn + j2);
        float a3 = (j3 < NO) ? __ldg(bmdn + j3) : 0.f;
#pragma unroll 4
        for (int k = 0; k < NU; k++) {
            float hv = __ldcg(h3p + k*NB);
            const float* wr = Wmdn + k*NO;
            a0 = fmaf(hv, __ldg(wr + j0), a0);
            a1 = fmaf(hv, __ldg(wr + j1), a1);
            a2 = fmaf(hv, __ldg(wr + j2), a2);
            a3 = fmaf(hv, (j3 < NO) ? __ldg(wr + j3) : 0.f, a3);
        }
        float v = (lane < 20) ? a0 : -INFINITY;
#pragma unroll
        for (int off = 16; off > 0; off >>= 1) v = fmaxf(v, __shfl_xor_sync(FULL, v, off));
        float e = (lane < 20) ? expf(a0 - v) : 0.f;
        float s = e;
#pragma unroll
        for (int off = 16; off > 0; off >>= 1) s += __shfl_xor_sync(FULL, s, off);

        float* op = out + (bb*NT + tt)*NO;
        op[j0] = (lane < 20) ? (e / s) : a0;       // pi | mu1
        op[j1] = (j1 >= 60) ? expf(a1) : a1;       // mu | s1(60-63)
        op[j2] = expf(a2);                         // s1/s2
        if (j3 < NO) {
            float o3;
            if (j3 < 100)      o3 = expf(a3);      // s2
            else if (j3 < 120) o3 = tanhf(a3);     // rho
            else               o3 = sigf(a3);      // eos
            op[j3] = o3;
        }
    }
}

// =====================================================================
// launch
// =====================================================================
extern "C" void kernel_launch(void* const* d_in, const int* in_sizes, int n_in,
                              void* d_out, int out_size)
{
    const float* strokes = (const float*)d_in[0];
    const int*   chars   = (const int*)  d_in[1];
    const int*   lens    = (const int*)  d_in[2];
    const float* Wx0 = (const float*)d_in[3];
    const float* Wh0 = (const float*)d_in[4];
    const float* b0  = (const float*)d_in[5];
    const float* p0  = (const float*)d_in[6];
    const float* Wx1 = (const float*)d_in[7];
    const float* Wh1 = (const float*)d_in[8];
    const float* b1  = (const float*)d_in[9];
    const float* p1  = (const float*)d_in[10];
    const float* Wx2 = (const float*)d_in[11];
    const float* Wh2 = (const float*)d_in[12];
    const float* b2  = (const float*)d_in[13];
    const float* p2  = (const float*)d_in[14];
    const float* Watt = (const float*)d_in[15];
    const float* batt = (const float*)d_in[16];
    const float* Wmdn = (const float*)d_in[17];
    const float* bmdn = (const float*)d_in[18];
    float* out = (float*)d_out;

    static int smem_set = 0;
    const int SMEM_BYTES = (12800 + 2336 + 2048 + 608) * 4;   // 71168
    if (!smem_set) {
        cudaFuncSetAttribute(rnn_kernel, cudaFuncAttributeMaxDynamicSharedMemorySize, SMEM_BYTES);
        smem_set = 1;
    }

    pack_kernel<<<256, 256>>>(Wx0, Wh0, Wx1, Wh1, Wx2, Wh2);
    rnn_kernel<<<NCTA, NTH, SMEM_BYTES>>>(strokes, chars, lens,
                                          b0, p0, b1, p1, b2, p2,
                                          Watt, batt, Wmdn, bmdn, out);
}

// round 8
// speedup vs baseline: 1.0195x; 1.0195x over previous
#include <cuda_runtime.h>
#include <math.h>

#define NB 32      // batch
#define NT 400     // timesteps
#define NU 400     // LSTM units
#define NKG 10     // attention gaussians
#define NC 73      // alphabet
#define NUC 50     // char positions
#define NO 121     // MDN outputs
#define H4 1600    // 4*NU
#define NCTA 150
#define NTH 256
#define NWARP 8

typedef unsigned long long ull;
#define ull2 ulonglong2

// ---------------- packed weights (gate-interleaved float4 per (u,k)) ----------------
__device__ float4 d_P0  [NU*476];  // layer1: [x(3), w(73), h1(400)]
__device__ float4 d_P1r [NU*403];  // layer2 recurrent: [x(3), h2(400)]
__device__ float4 d_P1h [NU*400];  // layer2 h1 part of Wx1
__device__ float4 d_P1w [NU*73];   // layer2 w part of Wx1
__device__ float4 d_P2r [NU*403];  // layer3 recurrent: [x(3), h3(400)]
__device__ float4 d_P2wh[NU*473];  // layer3 [w(73), h2(400)] part of Wx2

// ---------------- state, transposed [u][b] ----------------
__device__ float d_h1a[NU*NB];
__device__ float d_h1b[NU*NB];
__device__ float d_h2 [NU*NB];
__device__ float d_h3 [NU*NB];
__device__ float d_Z2p[NU*4*NB];
__device__ float d_R3p[NU*4*NB];
__device__ float d_wT [NC*NB];
__device__ float d_h3all[NT*NU*NB];

// ---------------- sync state ----------------
__device__ unsigned d_arr[160];     // per-CTA barrier arrival slots
__device__ unsigned d_release;      // barrier release flag
__device__ unsigned d_flags[64];    // [0..49]: h2 ready; [50..53]: w ready

// =====================================================================
// pack kernel: gate-interleave weights + zero state/sync
// =====================================================================
__global__ void pack_kernel(const float* __restrict__ Wx0, const float* __restrict__ Wh0,
                            const float* __restrict__ Wx1, const float* __restrict__ Wh1,
                            const float* __restrict__ Wx2, const float* __restrict__ Wh2)
{
    int idx = blockIdx.x * blockDim.x + threadIdx.x;
    int str = gridDim.x * blockDim.x;

    for (int e = idx; e < 160; e += str) d_arr[e] = 0u;
    for (int e = idx; e < 64; e += str) d_flags[e] = 0u;
    if (idx == 0) d_release = 0u;
    for (int e = idx; e < NU*NB; e += str) {
        d_h1a[e] = 0.f; d_h1b[e] = 0.f; d_h2[e] = 0.f; d_h3[e] = 0.f;
    }
    for (int e = idx; e < NC*NB; e += str) d_wT[e] = 0.f;

    for (int e = idx; e < NU*476; e += str) {
        int u = e / 476, k = e - u*476;
        const float* s = (k < 76) ? (Wx0 + k*H4) : (Wh0 + (k-76)*H4);
        d_P0[e] = make_float4(s[u], s[NU+u], s[2*NU+u], s[3*NU+u]);
    }
    for (int e = idx; e < NU*403; e += str) {
        int u = e / 403, k = e - u*403;
        const float* s = (k < 3) ? (Wx1 + k*H4) : (Wh1 + (k-3)*H4);
        d_P1r[e] = make_float4(s[u], s[NU+u], s[2*NU+u], s[3*NU+u]);
    }
    for (int e = idx; e < NU*400; e += str) {
        int u = e / 400, k = e - u*400;
        const float* s = Wx1 + (76+k)*H4;
        d_P1h[e] = make_float4(s[u], s[NU+u], s[2*NU+u], s[3*NU+u]);
    }
    for (int e = idx; e < NU*73; e += str) {
        int u = e / 73, k = e - u*73;
        const float* s = Wx1 + (3+k)*H4;
        d_P1w[e] = make_float4(s[u], s[NU+u], s[2*NU+u], s[3*NU+u]);
    }
    for (int e = idx; e < NU*403; e += str) {
        int u = e / 403, k = e - u*403;
        const float* s = (k < 3) ? (Wx2 + k*H4) : (Wh2 + (k-3)*H4);
        d_P2r[e] = make_float4(s[u], s[NU+u], s[2*NU+u], s[3*NU+u]);
    }
    for (int e = idx; e < NU*473; e += str) {
        int u = e / 473, k = e - u*473;
        const float* s = Wx2 + (3+k)*H4;
        d_P2wh[e] = make_float4(s[u], s[NU+u], s[2*NU+u], s[3*NU+u]);
    }
}

// =====================================================================
// helpers
// =====================================================================
__device__ __forceinline__ float sigf(float x) { return 1.f / (1.f + expf(-x)); }

__device__ __forceinline__ ull pk2(float v) {
    ull r; asm("mov.b64 %0, {%1, %1};" : "=l"(r) : "f"(v)); return r;
}
__device__ __forceinline__ ull pk(float lo, float hi) {
    ull r; asm("mov.b64 %0, {%1, %2};" : "=l"(r) : "f"(lo), "f"(hi)); return r;
}
__device__ __forceinline__ void upk(ull v, float& lo, float& hi) {
    asm("mov.b64 {%0, %1}, %2;" : "=f"(lo), "=f"(hi) : "l"(v));
}
__device__ __forceinline__ void fma2(ull& d, ull a, ull b) {
    asm("fma.rn.f32x2 %0, %1, %2, %0;" : "+l"(d) : "l"(a), "l"(b));
}

__device__ __forceinline__ void st_rel(unsigned* p, unsigned v) {
    asm volatile("{ .reg .u64 a; cvta.to.global.u64 a, %0; st.release.gpu.global.u32 [a], %1; }"
                 :: "l"(p), "r"(v) : "memory");
}
__device__ __forceinline__ unsigned ld_acq(const unsigned* p) {
    unsigned v;
    asm volatile("{ .reg .u64 a; cvta.to.global.u64 a, %1; ld.acquire.gpu.global.u32 %0, [a]; }"
                 : "=r"(v) : "l"(p) : "memory");
    return v;
}

// barrier: per-CTA release slots; CTA0 polls with ONE acquire load per thread
// (parallel across 150 threads), then release-stores the flag. No fence/IVALL.
__device__ __forceinline__ void gsync(unsigned r, int cta)
{
    __syncthreads();
    if (cta == 0) {
        int tid = threadIdx.x;
        if (tid > 0 && tid < NCTA) {
            while (ld_acq(d_arr + tid) < r) { }
        }
        __syncthreads();
        if (tid == 0) st_rel(&d_release, r);
    } else {
        if (threadIdx.x == 0) {
            st_rel(d_arr + cta, r);
            while (ld_acq(&d_release) < r) { }
        }
    }
    __syncthreads();
}

// bulk copy global(L2,.cg) -> shared
__device__ __forceinline__ void copy4(float* dst, const float* src, int nfl)
{
    const float4* s = (const float4*)src;
    float4* d = (float4*)dst;
    int n4 = nfl >> 2;
    for (int i = threadIdx.x; i < n4; i += NTH) d[i] = __ldcg(s + i);
}

// gate accumulation, unroll 8 for MLP
__device__ __forceinline__ void accseg(ull& a01, ull& a23,
                                       const ull2* __restrict__ P,
                                       const float* __restrict__ vs, int K, int b)
{
#pragma unroll 8
    for (int k = 0; k < K; k++) {
        ull hh = pk2(vs[k*NB + b]);
        ull2 w = __ldg(P + k);
        fma2(a01, w.x, hh);
        fma2(a23, w.y, hh);
    }
}

__device__ __forceinline__ void accx(ull& a01, ull& a23, const ull2* __restrict__ P,
                                     float x0, float x1, float x2)
{
    ull2 w0 = __ldg(P+0), w1 = __ldg(P+1), w2 = __ldg(P+2);
    ull X0 = pk2(x0), X1 = pk2(x1), X2 = pk2(x2);
    fma2(a01, w0.x, X0); fma2(a23, w0.y, X0);
    fma2(a01, w1.x, X1); fma2(a23, w1.y, X1);
    fma2(a01, w2.x, X2); fma2(a23, w2.y, X2);
}

// =====================================================================
// persistent RNN kernel: 150 CTAs x 256 threads
// =====================================================================
__global__ void __launch_bounds__(NTH, 1)
rnn_kernel(const float* __restrict__ strokes,
           const int*   __restrict__ chars,
           const int*   __restrict__ lens,
           const float* __restrict__ b0, const float* __restrict__ p0,
           const float* __restrict__ b1, const float* __restrict__ p1,
           const float* __restrict__ b2, const float* __restrict__ p2,
           const float* __restrict__ Watt, const float* __restrict__ batt,
           const float* __restrict__ Wmdn, const float* __restrict__ bmdn,
           float* __restrict__ out)
{
    extern __shared__ float smem[];
    float* s_h   = smem;            // 12800: staged h-vector [k][b]
    float* s_wc  = smem + 12800;    // 2336: staged w-vector [k][b]
    float* s_red = smem + 15136;    // 8*128: stage-4 K-split partials
    float* s_att = smem + 16160;    // 8*76: attention scatter scratch

    const int cta  = blockIdx.x;
    const int tid  = threadIdx.x;
    const int lane = tid & 31;
    const int wib  = tid >> 5;
    const int b    = lane;
    const unsigned FULL = 0xffffffffu;

    // register-resident recurrent state (stable warp<->unit maps)
    float c1reg = 0.f;   // CTAs 0-49: unit = cta*8+wib
    float c2reg = 0.f;   // CTAs 0-49: same unit
    float c3reg = 0.f;   // CTAs 50-149, wib<4: unit = (cta-50)*4+wib
    float kapreg = 0.f;  // CTAs 100-103, warp=batch, lane<10

    for (int t = 0; t < NT; t++) {
        const float* h1prev = (t & 1) ? d_h1b : d_h1a;
        float*       h1cur  = (t & 1) ? d_h1a : d_h1b;
        const float* xp = strokes + (b*NT + t)*3;

        // ======== stage 1: z1+LSTM1 (0-49) | R2 (50-99) | R3 (100-149), 1 warp/unit ========
        if (cta < 50) {
            copy4(s_h,  h1prev, NU*NB);
            copy4(s_wc, d_wT,   NC*NB);
            __syncthreads();
            int u = cta*8 + wib;
            ull a01 = pk(__ldg(b0+u),      __ldg(b0+NU+u));
            ull a23 = pk(__ldg(b0+2*NU+u), __ldg(b0+3*NU+u));
            const ull2* P = (const ull2*)(d_P0 + u*476);
            accx(a01, a23, P, __ldg(xp), __ldg(xp+1), __ldg(xp+2));
            accseg(a01, a23, P+3,  s_wc, NC, b);
            accseg(a01, a23, P+76, s_h,  NU, b);
            float zi,zf,zg,zo; upk(a01,zi,zf); upk(a23,zg,zo);
            float ig = sigf(zi + __ldg(p0+u)      * c1reg);
            float fg = sigf(zf + __ldg(p0+NU+u)   * c1reg);
            float cn = fg*c1reg + ig*tanhf(zg);
            float og = sigf(zo + __ldg(p0+2*NU+u) * cn);
            c1reg = cn;
            __stcg(&h1cur[u*NB + b], og * tanhf(cn));
        } else if (cta < 100) {
            copy4(s_h, d_h2, NU*NB);
            __syncthreads();
            int u = (cta-50)*8 + wib;
            ull a01 = pk(__ldg(b1+u),      __ldg(b1+NU+u));
            ull a23 = pk(__ldg(b1+2*NU+u), __ldg(b1+3*NU+u));
            const ull2* P = (const ull2*)(d_P1r + u*403);
            accx(a01, a23, P, __ldg(xp), __ldg(xp+1), __ldg(xp+2));
            accseg(a01, a23, P+3, s_h, NU, b);
            float g0,g1,g2,g3; upk(a01,g0,g1); upk(a23,g2,g3);
            float* dp = d_Z2p + u*128 + b;
            __stcg(dp+0,g0); __stcg(dp+32,g1); __stcg(dp+64,g2); __stcg(dp+96,g3);
        } else {
            copy4(s_h, d_h3, NU*NB);
            __syncthreads();
            int u = (cta-100)*8 + wib;
            ull a01 = pk(__ldg(b2+u),      __ldg(b2+NU+u));
            ull a23 = pk(__ldg(b2+2*NU+u), __ldg(b2+3*NU+u));
            const ull2* P = (const ull2*)(d_P2r + u*403);
            accx(a01, a23, P, __ldg(xp), __ldg(xp+1), __ldg(xp+2));
            accseg(a01, a23, P+3, s_h, NU, b);
            float g0,g1,g2,g3; upk(a01,g0,g1); upk(a23,g2,g3);
            float* dp = d_R3p + u*128 + b;
            __stcg(dp+0,g0); __stcg(dp+32,g1); __stcg(dp+64,g2); __stcg(dp+96,g3);
        }
        gsync(2*t + 1, cta);

        // ======== stage 2/3: Z2h + attention(w) -> z2+LSTM2 ========
        if (cta < 50) {
            copy4(s_h, h1cur, NU*NB);
            __syncthreads();
            int u = cta*8 + wib;
            // init acc from Z2p (includes bias), add h1 part
            const float* zp = d_Z2p + u*128 + b;
            ull a01 = pk(__ldcg(zp), __ldcg(zp+32));
            ull a23 = pk(__ldcg(zp+64), __ldcg(zp+96));
            accseg(a01, a23, (const ull2*)(d_P1h + u*400), s_h, NU, b);
            // wait for attention w (parallel acquire, one flag/thread)
            if (tid < 4) { while (ld_acq(d_flags + 50 + tid) < (unsigned)(t+1)) { } }
            __syncthreads();
            copy4(s_wc, d_wT, NC*NB);
            __syncthreads();
            accseg(a01, a23, (const ull2*)(d_P1w + u*73), s_wc, NC, b);
            float zi,zf,zg,zo; upk(a01,zi,zf); upk(a23,zg,zo);
            float ig = sigf(zi + __ldg(p1+u)      * c2reg);
            float fg = sigf(zf + __ldg(p1+NU+u)   * c2reg);
            float cn = fg*c2reg + ig*tanhf(zg);
            float og = sigf(zo + __ldg(p1+2*NU+u) * cn);
            c2reg = cn;
            __stcg(&d_h2[u*NB + b], og * tanhf(cn));
            __syncthreads();
            if (tid == 0) st_rel(d_flags + cta, (unsigned)(t+1));   // h2 ready
        } else if (cta >= 100 && cta < 104) {
            // attention: warp <-> batch, full K=400
            copy4(s_h, h1cur, NU*NB);
            __syncthreads();
            int ab = (cta-100)*8 + wib;
            float att = 0.f;
            if (lane < 30) {
                float acc = __ldg(batt + lane);
#pragma unroll 8
                for (int k = 0; k < NU; k++)
                    acc = fmaf(s_h[k*NB + ab], __ldg(Watt + k*30 + lane), acc);
                att = acc;
            }
            float ah = __shfl_sync(FULL, att, (lane < 10) ? lane      : 0);
            float bh = __shfl_sync(FULL, att, (lane < 10) ? lane + 10 : 10);
            float kh = __shfl_sync(FULL, att, (lane < 10) ? lane + 20 : 20);
            float alpha = 0.f, beta = 0.f;
            if (lane < 10) {
                alpha = expf(ah);
                beta  = expf(bh);
                kapreg = kapreg + expf(kh);
            }
            float* sw = s_att + wib*76;
            for (int c = lane; c < NC; c += 32) sw[c] = 0.f;
            __syncwarp();
            int lb = __ldg(lens + ab);
#pragma unroll
            for (int hh = 0; hh < 2; hh++) {
                int uu = lane + hh*32;
                float phi = 0.f;
#pragma unroll
                for (int g = 0; g < NKG; g++) {
                    float ag = __shfl_sync(FULL, alpha,  g);
                    float bg = __shfl_sync(FULL, beta,   g);
                    float kg = __shfl_sync(FULL, kapreg, g);
                    float df = kg - (float)uu;
                    phi = fmaf(ag, expf(-bg*df*df), phi);
                }
                if (uu < NUC && uu < lb) {
                    int c = __ldg(chars + ab*NUC + uu);
                    atomicAdd(&sw[c], phi);
                }
            }
            __syncwarp();
            for (int c = lane; c < NC; c += 32) __stcg(&d_wT[c*NB + ab], sw[c]);
            __syncthreads();
            if (tid == 0) st_rel(d_flags + 50 + (cta-100), (unsigned)(t+1));  // w ready
        }

        // ======== stage 4 (CTAs 50-149): z3 = R3p + [w,h2]@P2wh, 2-warp split ========
        if (cta >= 50) {
            if (tid < 54) { while (ld_acq(d_flags + tid) < (unsigned)(t+1)) { } }
            __syncthreads();
            copy4(s_h,  d_h2, NU*NB);
            copy4(s_wc, d_wT, NC*NB);
            __syncthreads();
            {
                int j = wib >> 1, q = wib & 1;
                int u = (cta-50)*4 + j;
                ull a01 = 0ull, a23 = 0ull;
                const ull2* P = (const ull2*)(d_P2wh + u*473);
                if (q == 0) {
                    accseg(a01, a23, P,    s_wc, NC, b);            // w (73)
                    accseg(a01, a23, P+73, s_h, 164, b);            // h2[0:164)
                } else {
                    accseg(a01, a23, P+237, s_h + 164*NB, 236, b);  // h2[164:400)
                }
                float g0,g1,g2,g3; upk(a01,g0,g1); upk(a23,g2,g3);
                float* rp = s_red + wib*128 + b;
                rp[0]=g0; rp[32]=g1; rp[64]=g2; rp[96]=g3;
            }
            __syncthreads();
            if (wib < 4) {
                int uu = (cta-50)*4 + wib;
                int o4 = uu*128 + b;
                const float* r0 = s_red + (2*wib)*128 + b;
                const float* r1 = s_red + (2*wib+1)*128 + b;
                float zi = __ldcg(d_R3p+o4)    + r0[0]  + r1[0];
                float zf = __ldcg(d_R3p+o4+32) + r0[32] + r1[32];
                float zg = __ldcg(d_R3p+o4+64) + r0[64] + r1[64];
                float zo = __ldcg(d_R3p+o4+96) + r0[96] + r1[96];
                float ig = sigf(zi + __ldg(p2+uu)      * c3reg);
                float fg = sigf(zf + __ldg(p2+NU+uu)   * c3reg);
                float cn = fg*c3reg + ig*tanhf(zg);
                float og = sigf(zo + __ldg(p2+2*NU+uu) * cn);
                c3reg = cn;
                float hv = og * tanhf(cn);
                __stcg(&d_h3[uu*NB + b], hv);
                __stcg(&d_h3all[(t*NU + uu)*NB + b], hv);
            }
        }
        gsync(2*t + 2, cta);
    }

    // ================= MDN head =================
    const int gw = cta*NWARP + wib;
    const int NW = NCTA*NWARP;
    for (int task = gw; task < NB*NT; task += NW) {
        int bb = task / NT;
        int tt = task - bb*NT;
        const float* h3p = d_h3all + (tt*NU)*NB + bb;

        int j0 = lane, j1 = lane + 32, j2 = lane + 64, j3 = lane + 96;
        float a0 = __ldg(bmdn + j0);
        float a1 = __ldg(bmdn + j1);
        float a2 = __ldg(bmdn + j2);
        float a3 = (j3 < NO) ? __ldg(bmdn + j3) : 0.f;
#pragma unroll 4
        for (int k = 0; k < NU; k++) {
            float hv = __ldcg(h3p + k*NB);
            const float* wr = Wmdn + k*NO;
            a0 = fmaf(hv, __ldg(wr + j0), a0);
            a1 = fmaf(hv, __ldg(wr + j1), a1);
            a2 = fmaf(hv, __ldg(wr + j2), a2);
            a3 = fmaf(hv, (j3 < NO) ? __ldg(wr + j3) : 0.f, a3);
        }
        float v = (lane < 20) ? a0 : -INFINITY;
#pragma unroll
        for (int off = 16; off > 0; off >>= 1) v = fmaxf(v, __shfl_xor_sync(FULL, v, off));
        float e = (lane < 20) ? expf(a0 - v) : 0.f;
        float s = e;
#pragma unroll
        for (int off = 16; off > 0; off >>= 1) s += __shfl_xor_sync(FULL, s, off);

        float* op = out + (bb*NT + tt)*NO;
        op[j0] = (lane < 20) ? (e / s) : a0;       // pi | mu1
        op[j1] = (j1 >= 60) ? expf(a1) : a1;       // mu | s1(60-63)
        op[j2] = expf(a2);                         // s1/s2
        if (j3 < NO) {
            float o3;
            if (j3 < 100)      o3 = expf(a3);      // s2
            else if (j3 < 120) o3 = tanhf(a3);     // rho
            else               o3 = sigf(a3);      // eos
            op[j3] = o3;
        }
    }
}

// =====================================================================
// launch
// =====================================================================
extern "C" void kernel_launch(void* const* d_in, const int* in_sizes, int n_in,
                              void* d_out, int out_size)
{
    const float* strokes = (const float*)d_in[0];
    const int*   chars   = (const int*)  d_in[1];
    const int*   lens    = (const int*)  d_in[2];
    const float* Wx0 = (const float*)d_in[3];
    const float* Wh0 = (const float*)d_in[4];
    const float* b0  = (const float*)d_in[5];
    const float* p0  = (const float*)d_in[6];
    const float* Wx1 = (const float*)d_in[7];
    const float* Wh1 = (const float*)d_in[8];
    const float* b1  = (const float*)d_in[9];
    const float* p1  = (const float*)d_in[10];
    const float* Wx2 = (const float*)d_in[11];
    const float* Wh2 = (const float*)d_in[12];
    const float* b2  = (const float*)d_in[13];
    const float* p2  = (const float*)d_in[14];
    const float* Watt = (const float*)d_in[15];
    const float* batt = (const float*)d_in[16];
    const float* Wmdn = (const float*)d_in[17];
    const float* bmdn = (const float*)d_in[18];
    float* out = (float*)d_out;

    static int smem_set = 0;
    const int SMEM_BYTES = (12800 + 2336 + 1024 + 608) * 4;   // 67072
    if (!smem_set) {
        cudaFuncSetAttribute(rnn_kernel, cudaFuncAttributeMaxDynamicSharedMemorySize, SMEM_BYTES);
        smem_set = 1;
    }

    pack_kernel<<<256, 256>>>(Wx0, Wh0, Wx1, Wh1, Wx2, Wh2);
    rnn_kernel<<<NCTA, NTH, SMEM_BYTES>>>(strokes, chars, lens,
                                          b0, p0, b1, p1, b2, p2,
                                          Watt, batt, Wmdn, bmdn, out);
}

// round 9
// speedup vs baseline: 1.0707x; 1.0502x over previous
#include <cuda_runtime.h>
#include <math.h>

#define NB 32      // batch
#define NT 400     // timesteps
#define NU 400     // LSTM units
#define NKG 10     // attention gaussians
#define NC 73      // alphabet
#define NUC 50     // char positions
#define NO 121     // MDN outputs
#define H4 1600    // 4*NU
#define NCTA 150
#define NTH 256
#define NWARP 8
#define SLOT 32    // 128B padding stride for sync words

typedef unsigned long long ull;
#define ull2 ulonglong2

// ---------------- packed weights (gate-interleaved float4 per (u,k)) ----------------
__device__ float4 d_P0  [NU*476];  // layer1: [x(3), w(73), h1(400)]
__device__ float4 d_P1r [NU*403];  // layer2 recurrent: [x(3), h2(400)]
__device__ float4 d_P1h [NU*400];  // layer2 h1 part of Wx1
__device__ float4 d_P1w [NU*73];   // layer2 w part of Wx1
__device__ float4 d_P2r [NU*403];  // layer3 recurrent: [x(3), h3(400)]
__device__ float4 d_P2wh[NU*473];  // layer3 [w(73), h2(400)] part of Wx2

// ---------------- state, transposed [u][b] ----------------
__device__ float d_h1a[NU*NB];
__device__ float d_h1b[NU*NB];
__device__ float d_h2 [NU*NB];
__device__ float d_h3 [NU*NB];
__device__ float d_Z2p[NU*4*NB];
__device__ float d_R3p[NU*4*NB];
__device__ float d_wT [NC*NB];
__device__ float d_h3all[NT*NU*NB];

// ---------------- sync state: each word on its own 128B line ----------------
__device__ unsigned d_arr[NCTA*SLOT];    // per-CTA barrier arrival slots
__device__ unsigned d_rel[SLOT];         // barrier release flag
__device__ unsigned d_flags[64*SLOT];    // [0..49]: h2 ready; [50..53]: w ready

// =====================================================================
// pack kernel: gate-interleave weights + zero state/sync
// =====================================================================
__global__ void pack_kernel(const float* __restrict__ Wx0, const float* __restrict__ Wh0,
                            const float* __restrict__ Wx1, const float* __restrict__ Wh1,
                            const float* __restrict__ Wx2, const float* __restrict__ Wh2)
{
    int idx = blockIdx.x * blockDim.x + threadIdx.x;
    int str = gridDim.x * blockDim.x;

    for (int e = idx; e < NCTA*SLOT; e += str) d_arr[e] = 0u;
    for (int e = idx; e < 64*SLOT; e += str) d_flags[e] = 0u;
    for (int e = idx; e < SLOT; e += str) d_rel[e] = 0u;
    for (int e = idx; e < NU*NB; e += str) {
        d_h1a[e] = 0.f; d_h1b[e] = 0.f; d_h2[e] = 0.f; d_h3[e] = 0.f;
    }
    for (int e = idx; e < NC*NB; e += str) d_wT[e] = 0.f;

    for (int e = idx; e < NU*476; e += str) {
        int u = e / 476, k = e - u*476;
        const float* s = (k < 76) ? (Wx0 + k*H4) : (Wh0 + (k-76)*H4);
        d_P0[e] = make_float4(s[u], s[NU+u], s[2*NU+u], s[3*NU+u]);
    }
    for (int e = idx; e < NU*403; e += str) {
        int u = e / 403, k = e - u*403;
        const float* s = (k < 3) ? (Wx1 + k*H4) : (Wh1 + (k-3)*H4);
        d_P1r[e] = make_float4(s[u], s[NU+u], s[2*NU+u], s[3*NU+u]);
    }
    for (int e = idx; e < NU*400; e += str) {
        int u = e / 400, k = e - u*400;
        const float* s = Wx1 + (76+k)*H4;
        d_P1h[e] = make_float4(s[u], s[NU+u], s[2*NU+u], s[3*NU+u]);
    }
    for (int e = idx; e < NU*73; e += str) {
        int u = e / 73, k = e - u*73;
        const float* s = Wx1 + (3+k)*H4;
        d_P1w[e] = make_float4(s[u], s[NU+u], s[2*NU+u], s[3*NU+u]);
    }
    for (int e = idx; e < NU*403; e += str) {
        int u = e / 403, k = e - u*403;
        const float* s = (k < 3) ? (Wx2 + k*H4) : (Wh2 + (k-3)*H4);
        d_P2r[e] = make_float4(s[u], s[NU+u], s[2*NU+u], s[3*NU+u]);
    }
    for (int e = idx; e < NU*473; e += str) {
        int u = e / 473, k = e - u*473;
        const float* s = Wx2 + (3+k)*H4;
        d_P2wh[e] = make_float4(s[u], s[NU+u], s[2*NU+u], s[3*NU+u]);
    }
}

// =====================================================================
// helpers
// =====================================================================
__device__ __forceinline__ float sigf(float x) { return 1.f / (1.f + expf(-x)); }

__device__ __forceinline__ ull pk2(float v) {
    ull r; asm("mov.b64 %0, {%1, %1};" : "=l"(r) : "f"(v)); return r;
}
__device__ __forceinline__ ull pk(float lo, float hi) {
    ull r; asm("mov.b64 %0, {%1, %2};" : "=l"(r) : "f"(lo), "f"(hi)); return r;
}
__device__ __forceinline__ void upk(ull v, float& lo, float& hi) {
    asm("mov.b64 {%0, %1}, %2;" : "=f"(lo), "=f"(hi) : "l"(v));
}
__device__ __forceinline__ void fma2(ull& d, ull a, ull b) {
    asm("fma.rn.f32x2 %0, %1, %2, %0;" : "+l"(d) : "l"(a), "l"(b));
}

__device__ __forceinline__ void st_rel(unsigned* p, unsigned v) {
    asm volatile("{ .reg .u64 a; cvta.to.global.u64 a, %0; st.release.gpu.global.u32 [a], %1; }"
                 :: "l"(p), "r"(v) : "memory");
}
__device__ __forceinline__ unsigned ld_acq(const unsigned* p) {
    unsigned v;
    asm volatile("{ .reg .u64 a; cvta.to.global.u64 a, %1; ld.acquire.gpu.global.u32 %0, [a]; }"
                 : "=r"(v) : "l"(p) : "memory");
    return v;
}
__device__ __forceinline__ void npause(unsigned ns) {
    asm volatile("nanosleep.u32 %0;" :: "r"(ns));
}
// polite spin: fast-path check, then backoff polling
__device__ __forceinline__ void wait_ge(const unsigned* p, unsigned r) {
    if (ld_acq(p) >= r) return;
    while (true) {
        npause(60);
        if (ld_acq(p) >= r) return;
    }
}

// barrier: per-CTA padded release slots; CTA0 polls (one slot per thread, with
// backoff), then release-stores padded flag. No fence/IVALL, no poll storms.
__device__ __forceinline__ void gsync(unsigned r, int cta)
{
    __syncthreads();
    if (cta == 0) {
        int tid = threadIdx.x;
        if (tid > 0 && tid < NCTA) wait_ge(d_arr + tid*SLOT, r);
        __syncthreads();
        if (tid == 0) st_rel(d_rel, r);
    } else {
        if (threadIdx.x == 0) {
            st_rel(d_arr + cta*SLOT, r);
            wait_ge(d_rel, r);
        }
    }
    __syncthreads();
}

// bulk copy global(L2,.cg) -> shared
__device__ __forceinline__ void copy4(float* dst, const float* src, int nfl)
{
    const float4* s = (const float4*)src;
    float4* d = (float4*)dst;
    int n4 = nfl >> 2;
    for (int i = threadIdx.x; i < n4; i += NTH) d[i] = __ldcg(s + i);
}

// gate accumulation, unroll 8 for MLP
__device__ __forceinline__ void accseg(ull& a01, ull& a23,
                                       const ull2* __restrict__ P,
                                       const float* __restrict__ vs, int K, int b)
{
#pragma unroll 8
    for (int k = 0; k < K; k++) {
        ull hh = pk2(vs[k*NB + b]);
        ull2 w = __ldg(P + k);
        fma2(a01, w.x, hh);
        fma2(a23, w.y, hh);
    }
}

__device__ __forceinline__ void accx(ull& a01, ull& a23, const ull2* __restrict__ P,
                                     float x0, float x1, float x2)
{
    ull2 w0 = __ldg(P+0), w1 = __ldg(P+1), w2 = __ldg(P+2);
    ull X0 = pk2(x0), X1 = pk2(x1), X2 = pk2(x2);
    fma2(a01, w0.x, X0); fma2(a23, w0.y, X0);
    fma2(a01, w1.x, X1); fma2(a23, w1.y, X1);
    fma2(a01, w2.x, X2); fma2(a23, w2.y, X2);
}

// =====================================================================
// persistent RNN kernel: 150 CTAs x 256 threads
// =====================================================================
__global__ void __launch_bounds__(NTH, 1)
rnn_kernel(const float* __restrict__ strokes,
           const int*   __restrict__ chars,
           const int*   __restrict__ lens,
           const float* __restrict__ b0, const float* __restrict__ p0,
           const float* __restrict__ b1, const float* __restrict__ p1,
           const float* __restrict__ b2, const float* __restrict__ p2,
           const float* __restrict__ Watt, const float* __restrict__ batt,
           const float* __restrict__ Wmdn, const float* __restrict__ bmdn,
           float* __restrict__ out)
{
    extern __shared__ float smem[];
    float* s_h   = smem;            // 12800: staged h-vector [k][b]
    float* s_wc  = smem + 12800;    // 2336: staged w-vector [k][b]
    float* s_red = smem + 15136;    // 8*128: stage-4 K-split partials
    float* s_att = smem + 16160;    // 8*76: attention scatter scratch

    const int cta  = blockIdx.x;
    const int tid  = threadIdx.x;
    const int lane = tid & 31;
    const int wib  = tid >> 5;
    const int b    = lane;
    const unsigned FULL = 0xffffffffu;

    // register-resident recurrent state (stable warp<->unit maps)
    float c1reg = 0.f;   // CTAs 0-49: unit = cta*8+wib
    float c2reg = 0.f;   // CTAs 0-49: same unit
    float c3reg = 0.f;   // CTAs 50-149, wib<4: unit = (cta-50)*4+wib
    float kapreg = 0.f;  // CTAs 100-103, warp=batch, lane<10

    for (int t = 0; t < NT; t++) {
        const float* h1prev = (t & 1) ? d_h1b : d_h1a;
        float*       h1cur  = (t & 1) ? d_h1a : d_h1b;
        const float* xp = strokes + (b*NT + t)*3;

        // ======== stage 1: z1+LSTM1 (0-49) | R2 (50-99) | R3 (100-149), 1 warp/unit ========
        if (cta < 50) {
            copy4(s_h,  h1prev, NU*NB);
            copy4(s_wc, d_wT,   NC*NB);
            __syncthreads();
            int u = cta*8 + wib;
            ull a01 = pk(__ldg(b0+u),      __ldg(b0+NU+u));
            ull a23 = pk(__ldg(b0+2*NU+u), __ldg(b0+3*NU+u));
            const ull2* P = (const ull2*)(d_P0 + u*476);
            accx(a01, a23, P, __ldg(xp), __ldg(xp+1), __ldg(xp+2));
            accseg(a01, a23, P+3,  s_wc, NC, b);
            accseg(a01, a23, P+76, s_h,  NU, b);
            float zi,zf,zg,zo; upk(a01,zi,zf); upk(a23,zg,zo);
            float ig = sigf(zi + __ldg(p0+u)      * c1reg);
            float fg = sigf(zf + __ldg(p0+NU+u)   * c1reg);
            float cn = fg*c1reg + ig*tanhf(zg);
            float og = sigf(zo + __ldg(p0+2*NU+u) * cn);
            c1reg = cn;
            __stcg(&h1cur[u*NB + b], og * tanhf(cn));
        } else if (cta < 100) {
            copy4(s_h, d_h2, NU*NB);
            __syncthreads();
            int u = (cta-50)*8 + wib;
            ull a01 = pk(__ldg(b1+u),      __ldg(b1+NU+u));
            ull a23 = pk(__ldg(b1+2*NU+u), __ldg(b1+3*NU+u));
            const ull2* P = (const ull2*)(d_P1r + u*403);
            accx(a01, a23, P, __ldg(xp), __ldg(xp+1), __ldg(xp+2));
            accseg(a01, a23, P+3, s_h, NU, b);
            float g0,g1,g2,g3; upk(a01,g0,g1); upk(a23,g2,g3);
            float* dp = d_Z2p + u*128 + b;
            __stcg(dp+0,g0); __stcg(dp+32,g1); __stcg(dp+64,g2); __stcg(dp+96,g3);
        } else {
            copy4(s_h, d_h3, NU*NB);
            __syncthreads();
            int u = (cta-100)*8 + wib;
            ull a01 = pk(__ldg(b2+u),      __ldg(b2+NU+u));
            ull a23 = pk(__ldg(b2+2*NU+u), __ldg(b2+3*NU+u));
            const ull2* P = (const ull2*)(d_P2r + u*403);
            accx(a01, a23, P, __ldg(xp), __ldg(xp+1), __ldg(xp+2));
            accseg(a01, a23, P+3, s_h, NU, b);
            float g0,g1,g2,g3; upk(a01,g0,g1); upk(a23,g2,g3);
            float* dp = d_R3p + u*128 + b;
            __stcg(dp+0,g0); __stcg(dp+32,g1); __stcg(dp+64,g2); __stcg(dp+96,g3);
        }
        gsync(2*t + 1, cta);

        // ======== stage 2/3: Z2h + attention(w) -> z2+LSTM2 ========
        if (cta < 50) {
            copy4(s_h, h1cur, NU*NB);
            __syncthreads();
            int u = cta*8 + wib;
            // init acc from Z2p (includes bias), add h1 part
            const float* zp = d_Z2p + u*128 + b;
            ull a01 = pk(__ldcg(zp), __ldcg(zp+32));
            ull a23 = pk(__ldcg(zp+64), __ldcg(zp+96));
            accseg(a01, a23, (const ull2*)(d_P1h + u*400), s_h, NU, b);
            // wait for attention w (one padded flag per thread, backoff)
            if (tid < 4) wait_ge(d_flags + (50+tid)*SLOT, (unsigned)(t+1));
            __syncthreads();
            copy4(s_wc, d_wT, NC*NB);
            __syncthreads();
            accseg(a01, a23, (const ull2*)(d_P1w + u*73), s_wc, NC, b);
            float zi,zf,zg,zo; upk(a01,zi,zf); upk(a23,zg,zo);
            float ig = sigf(zi + __ldg(p1+u)      * c2reg);
            float fg = sigf(zf + __ldg(p1+NU+u)   * c2reg);
            float cn = fg*c2reg + ig*tanhf(zg);
            float og = sigf(zo + __ldg(p1+2*NU+u) * cn);
            c2reg = cn;
            __stcg(&d_h2[u*NB + b], og * tanhf(cn));
            __syncthreads();
            if (tid == 0) st_rel(d_flags + cta*SLOT, (unsigned)(t+1));   // h2 ready
        } else if (cta >= 100 && cta < 104) {
            // attention: warp <-> batch, full K=400
            copy4(s_h, h1cur, NU*NB);
            __syncthreads();
            int ab = (cta-100)*8 + wib;
            float att = 0.f;
            if (lane < 30) {
                float acc = __ldg(batt + lane);
#pragma unroll 8
                for (int k = 0; k < NU; k++)
                    acc = fmaf(s_h[k*NB + ab], __ldg(Watt + k*30 + lane), acc);
                att = acc;
            }
            float ah = __shfl_sync(FULL, att, (lane < 10) ? lane      : 0);
            float bh = __shfl_sync(FULL, att, (lane < 10) ? lane + 10 : 10);
            float kh = __shfl_sync(FULL, att, (lane < 10) ? lane + 20 : 20);
            float alpha = 0.f, beta = 0.f;
            if (lane < 10) {
                alpha = expf(ah);
                beta  = expf(bh);
                kapreg = kapreg + expf(kh);
            }
            float* sw = s_att + wib*76;
            for (int c = lane; c < NC; c += 32) sw[c] = 0.f;
            __syncwarp();
            int lb = __ldg(lens + ab);
#pragma unroll
            for (int hh = 0; hh < 2; hh++) {
                int uu = lane + hh*32;
                float phi = 0.f;
#pragma unroll
                for (int g = 0; g < NKG; g++) {
                    float ag = __shfl_sync(FULL, alpha,  g);
                    float bg = __shfl_sync(FULL, beta,   g);
                    float kg = __shfl_sync(FULL, kapreg, g);
                    float df = kg - (float)uu;
                    phi = fmaf(ag, expf(-bg*df*df), phi);
                }
                if (uu < NUC && uu < lb) {
                    int c = __ldg(chars + ab*NUC + uu);
                    atomicAdd(&sw[c], phi);
                }
            }
            __syncwarp();
            for (int c = lane; c < NC; c += 32) __stcg(&d_wT[c*NB + ab], sw[c]);
            __syncthreads();
            if (tid == 0) st_rel(d_flags + (50 + cta-100)*SLOT, (unsigned)(t+1));  // w ready
        }

        // ======== stage 4 (CTAs 50-149): z3 = R3p + [w,h2]@P2wh, 2-warp split ========
        if (cta >= 50) {
            if (tid < 54) wait_ge(d_flags + tid*SLOT, (unsigned)(t+1));
            __syncthreads();
            copy4(s_h,  d_h2, NU*NB);
            copy4(s_wc, d_wT, NC*NB);
            __syncthreads();
            {
                int j = wib >> 1, q = wib & 1;
                int u = (cta-50)*4 + j;
                ull a01 = 0ull, a23 = 0ull;
                const ull2* P = (const ull2*)(d_P2wh + u*473);
                if (q == 0) {
                    accseg(a01, a23, P,    s_wc, NC, b);            // w (73)
                    accseg(a01, a23, P+73, s_h, 164, b);            // h2[0:164)
                } else {
                    accseg(a01, a23, P+237, s_h + 164*NB, 236, b);  // h2[164:400)
                }
                float g0,g1,g2,g3; upk(a01,g0,g1); upk(a23,g2,g3);
                float* rp = s_red + wib*128 + b;
                rp[0]=g0; rp[32]=g1; rp[64]=g2; rp[96]=g3;
            }
            __syncthreads();
            if (wib < 4) {
                int uu = (cta-50)*4 + wib;
                int o4 = uu*128 + b;
                const float* r0 = s_red + (2*wib)*128 + b;
                const float* r1 = s_red + (2*wib+1)*128 + b;
                float zi = __ldcg(d_R3p+o4)    + r0[0]  + r1[0];
                float zf = __ldcg(d_R3p+o4+32) + r0[32] + r1[32];
                float zg = __ldcg(d_R3p+o4+64) + r0[64] + r1[64];
                float zo = __ldcg(d_R3p+o4+96) + r0[96] + r1[96];
                float ig = sigf(zi + __ldg(p2+uu)      * c3reg);
                float fg = sigf(zf + __ldg(p2+NU+uu)   * c3reg);
                float cn = fg*c3reg + ig*tanhf(zg);
                float og = sigf(zo + __ldg(p2+2*NU+uu) * cn);
                c3reg = cn;
                float hv = og * tanhf(cn);
                __stcg(&d_h3[uu*NB + b], hv);
                __stcg(&d_h3all[(t*NU + uu)*NB + b], hv);
            }
        }
        gsync(2*t + 2, cta);
    }

    // ================= MDN head =================
    const int gw = cta*NWARP + wib;
    const int NW = NCTA*NWARP;
    for (int task = gw; task < NB*NT; task += NW) {
        int bb = task / NT;
        int tt = task - bb*NT;
        const float* h3p = d_h3all + (tt*NU)*NB + bb;

        int j0 = lane, j1 = lane + 32, j2 = lane + 64, j3 = lane + 96;
        float a0 = __ldg(bmdn + j0);
        float a1 = __ldg(bmdn + j1);
        float a2 = __ldg(bmdn + j2);
        float a3 = (j3 < NO) ? __ldg(bmdn + j3) : 0.f;
#pragma unroll 4
        for (int k = 0; k < NU; k++) {
            float hv = __ldcg(h3p + k*NB);
            const float* wr = Wmdn + k*NO;
            a0 = fmaf(hv, __ldg(wr + j0), a0);
            a1 = fmaf(hv, __ldg(wr + j1), a1);
            a2 = fmaf(hv, __ldg(wr + j2), a2);
            a3 = fmaf(hv, (j3 < NO) ? __ldg(wr + j3) : 0.f, a3);
        }
        float v = (lane < 20) ? a0 : -INFINITY;
#pragma unroll
        for (int off = 16; off > 0; off >>= 1) v = fmaxf(v, __shfl_xor_sync(FULL, v, off));
        float e = (lane < 20) ? expf(a0 - v) : 0.f;
        float s = e;
#pragma unroll
        for (int off = 16; off > 0; off >>= 1) s += __shfl_xor_sync(FULL, s, off);

        float* op = out + (bb*NT + tt)*NO;
        op[j0] = (lane < 20) ? (e / s) : a0;       // pi | mu1
        op[j1] = (j1 >= 60) ? expf(a1) : a1;       // mu | s1(60-63)
        op[j2] = expf(a2);                         // s1/s2
        if (j3 < NO) {
            float o3;
            if (j3 < 100)      o3 = expf(a3);      // s2
            else if (j3 < 120) o3 = tanhf(a3);     // rho
            else               o3 = sigf(a3);      // eos
            op[j3] = o3;
        }
    }
}

// =====================================================================
// launch
// =====================================================================
extern "C" void kernel_launch(void* const* d_in, const int* in_sizes, int n_in,
                              void* d_out, int out_size)
{
    const float* strokes = (const float*)d_in[0];
    const int*   chars   = (const int*)  d_in[1];
    const int*   lens    = (const int*)  d_in[2];
    const float* Wx0 = (const float*)d_in[3];
    const float* Wh0 = (const float*)d_in[4];
    const float* b0  = (const float*)d_in[5];
    const float* p0  = (const float*)d_in[6];
    const float* Wx1 = (const float*)d_in[7];
    const float* Wh1 = (const float*)d_in[8];
    const float* b1  = (const float*)d_in[9];
    const float* p1  = (const float*)d_in[10];
    const float* Wx2 = (const float*)d_in[11];
    const float* Wh2 = (const float*)d_in[12];
    const float* b2  = (const float*)d_in[13];
    const float* p2  = (const float*)d_in[14];
    const float* Watt = (const float*)d_in[15];
    const float* batt = (const float*)d_in[16];
    const float* Wmdn = (const float*)d_in[17];
    const float* bmdn = (const float*)d_in[18];
    float* out = (float*)d_out;

    static int smem_set = 0;
    const int SMEM_BYTES = (12800 + 2336 + 1024 + 608) * 4;   // 67072
    if (!smem_set) {
        cudaFuncSetAttribute(rnn_kernel, cudaFuncAttributeMaxDynamicSharedMemorySize, SMEM_BYTES);
        smem_set = 1;
    }

    pack_kernel<<<256, 256>>>(Wx0, Wh0, Wx1, Wh1, Wx2, Wh2);
    rnn_kernel<<<NCTA, NTH, SMEM_BYTES>>>(strokes, chars, lens,
                                          b0, p0, b1, p1, b2, p2,
                                          Watt, batt, Wmdn, bmdn, out);
}

// round 10
// speedup vs baseline: 1.4898x; 1.3914x over previous
#include <cuda_runtime.h>
#include <math.h>

#define NB 32      // batch
#define NT 400     // timesteps
#define NU 400     // LSTM units
#define NKG 10     // attention gaussians
#define NC 73      // alphabet
#define NUC 50     // char positions
#define NO 121     // MDN outputs
#define H4 1600    // 4*NU
#define NCTA 150
#define NTH 256
#define NWARP 8
#define SLOT 32    // 128B padding stride for sync words

typedef unsigned long long ull;
#define ull2 ulonglong2

// ---------------- packed weights (gate-interleaved float4 per (u,k)) ----------------
__device__ float4 d_P0  [NU*476];  // layer1: [x(3), w(73), h1(400)]
__device__ float4 d_P1r [NU*403];  // layer2 recurrent: [x(3), h2(400)]
__device__ float4 d_P1h [NU*400];  // layer2 h1 part of Wx1
__device__ float4 d_P1w [NU*73];   // layer2 w part of Wx1
__device__ float4 d_P2r [NU*403];  // layer3 recurrent: [x(3), h3(400)]
__device__ float4 d_P2wh[NU*473];  // layer3 [w(73), h2(400)] part of Wx2

// ---------------- state, transposed [u][b] ----------------
__device__ float d_h1a[NU*NB];
__device__ float d_h1b[NU*NB];
__device__ float d_h2 [NU*NB];
__device__ float d_h3 [NU*NB];
__device__ float d_Z2p[NU*4*NB];
__device__ float d_R3p[NU*4*NB];
__device__ float d_wT [NC*NB];
__device__ float d_h3all[NT*NU*NB];

// ---------------- sync state: each word on its own 128B line ----------------
__device__ unsigned d_arr[NCTA*SLOT];
__device__ unsigned d_rel[SLOT];
__device__ unsigned d_flags[64*SLOT];   // [0..49]: h2 ready; [50..53]: w ready

// =====================================================================
// pack kernel: gate-interleave weights + zero state/sync
// =====================================================================
__global__ void pack_kernel(const float* __restrict__ Wx0, const float* __restrict__ Wh0,
                            const float* __restrict__ Wx1, const float* __restrict__ Wh1,
                            const float* __restrict__ Wx2, const float* __restrict__ Wh2)
{
    int idx = blockIdx.x * blockDim.x + threadIdx.x;
    int str = gridDim.x * blockDim.x;

    for (int e = idx; e < NCTA*SLOT; e += str) d_arr[e] = 0u;
    for (int e = idx; e < 64*SLOT; e += str) d_flags[e] = 0u;
    for (int e = idx; e < SLOT; e += str) d_rel[e] = 0u;
    for (int e = idx; e < NU*NB; e += str) {
        d_h1a[e] = 0.f; d_h1b[e] = 0.f; d_h2[e] = 0.f; d_h3[e] = 0.f;
    }
    for (int e = idx; e < NC*NB; e += str) d_wT[e] = 0.f;

    for (int e = idx; e < NU*476; e += str) {
        int u = e / 476, k = e - u*476;
        const float* s = (k < 76) ? (Wx0 + k*H4) : (Wh0 + (k-76)*H4);
        d_P0[e] = make_float4(s[u], s[NU+u], s[2*NU+u], s[3*NU+u]);
    }
    for (int e = idx; e < NU*403; e += str) {
        int u = e / 403, k = e - u*403;
        const float* s = (k < 3) ? (Wx1 + k*H4) : (Wh1 + (k-3)*H4);
        d_P1r[e] = make_float4(s[u], s[NU+u], s[2*NU+u], s[3*NU+u]);
    }
    for (int e = idx; e < NU*400; e += str) {
        int u = e / 400, k = e - u*400;
        const float* s = Wx1 + (76+k)*H4;
        d_P1h[e] = make_float4(s[u], s[NU+u], s[2*NU+u], s[3*NU+u]);
    }
    for (int e = idx; e < NU*73; e += str) {
        int u = e / 73, k = e - u*73;
        const float* s = Wx1 + (3+k)*H4;
        d_P1w[e] = make_float4(s[u], s[NU+u], s[2*NU+u], s[3*NU+u]);
    }
    for (int e = idx; e < NU*403; e += str) {
        int u = e / 403, k = e - u*403;
        const float* s = (k < 3) ? (Wx2 + k*H4) : (Wh2 + (k-3)*H4);
        d_P2r[e] = make_float4(s[u], s[NU+u], s[2*NU+u], s[3*NU+u]);
    }
    for (int e = idx; e < NU*473; e += str) {
        int u = e / 473, k = e - u*473;
        const float* s = Wx2 + (3+k)*H4;
        d_P2wh[e] = make_float4(s[u], s[NU+u], s[2*NU+u], s[3*NU+u]);
    }
}

// =====================================================================
// helpers
// =====================================================================
__device__ __forceinline__ float sigf(float x) { return 1.f / (1.f + expf(-x)); }

__device__ __forceinline__ ull pk2(float v) {
    ull r; asm("mov.b64 %0, {%1, %1};" : "=l"(r) : "f"(v)); return r;
}
__device__ __forceinline__ ull pk(float lo, float hi) {
    ull r; asm("mov.b64 %0, {%1, %2};" : "=l"(r) : "f"(lo), "f"(hi)); return r;
}
__device__ __forceinline__ void upk(ull v, float& lo, float& hi) {
    asm("mov.b64 {%0, %1}, %2;" : "=f"(lo), "=f"(hi) : "l"(v));
}
__device__ __forceinline__ void fma2(ull& d, ull a, ull b) {
    asm("fma.rn.f32x2 %0, %1, %2, %0;" : "+l"(d) : "l"(a), "l"(b));
}

// weight load: L1 evict_last (pin weights in L1 against streaming eviction)
__device__ __forceinline__ ull2 ldw(const ull2* p) {
    ull2 r;
    asm("ld.global.nc.L1::evict_last.v2.b64 {%0, %1}, [%2];"
        : "=l"(r.x), "=l"(r.y) : "l"(p));
    return r;
}

__device__ __forceinline__ void st_rel(unsigned* p, unsigned v) {
    asm volatile("{ .reg .u64 a; cvta.to.global.u64 a, %0; st.release.gpu.global.u32 [a], %1; }"
                 :: "l"(p), "r"(v) : "memory");
}
// relaxed poll load: goes to L2 (strong scoped), NO acquire side-effects
__device__ __forceinline__ unsigned ld_rlx(const unsigned* p) {
    unsigned v;
    asm volatile("{ .reg .u64 a; cvta.to.global.u64 a, %1; ld.relaxed.gpu.global.u32 %0, [a]; }"
                 : "=r"(v) : "l"(p) : "memory");
    return v;
}
__device__ __forceinline__ void npause(unsigned ns) {
    asm volatile("nanosleep.u32 %0;" :: "r"(ns));
}
__device__ __forceinline__ void wait_ge(const unsigned* p, unsigned r) {
    if (ld_rlx(p) >= r) return;
    while (true) {
        npause(60);
        if (ld_rlx(p) >= r) return;
    }
}

// barrier: per-CTA padded release slots; CTA0 polls (relaxed, backoff), then
// release-stores padded flag. No fence/IVALL, no acquire anywhere.
__device__ __forceinline__ void gsync(unsigned r, int cta)
{
    __syncthreads();
    if (cta == 0) {
        int tid = threadIdx.x;
        if (tid > 0 && tid < NCTA) wait_ge(d_arr + tid*SLOT, r);
        __syncthreads();
        if (tid == 0) st_rel(d_rel, r);
    } else {
        if (threadIdx.x == 0) {
            st_rel(d_arr + cta*SLOT, r);
            wait_ge(d_rel, r);
        }
    }
    __syncthreads();
}

// staging copy: cp.async.cg = global->shared, GUARANTEED L1 bypass
__device__ __forceinline__ void copy4(float* dst, const float* src, int nfl)
{
    unsigned base = (unsigned)__cvta_generic_to_shared(dst);
    int n4 = nfl >> 2;
    for (int i = threadIdx.x; i < n4; i += NTH) {
        asm volatile("cp.async.cg.shared.global [%0], [%1], 16;"
                     :: "r"(base + i*16), "l"((const char*)src + i*16) : "memory");
    }
}
__device__ __forceinline__ void cpwait()
{
    asm volatile("cp.async.commit_group;" ::: "memory");
    asm volatile("cp.async.wait_group 0;" ::: "memory");
    __syncthreads();
}

// gate accumulation, unroll 8, weights pinned via evict_last
__device__ __forceinline__ void accseg(ull& a01, ull& a23,
                                       const ull2* __restrict__ P,
                                       const float* __restrict__ vs, int K, int b)
{
#pragma unroll 8
    for (int k = 0; k < K; k++) {
        ull hh = pk2(vs[k*NB + b]);
        ull2 w = ldw(P + k);
        fma2(a01, w.x, hh);
        fma2(a23, w.y, hh);
    }
}

__device__ __forceinline__ void accx(ull& a01, ull& a23, const ull2* __restrict__ P,
                                     float x0, float x1, float x2)
{
    ull2 w0 = ldw(P+0), w1 = ldw(P+1), w2 = ldw(P+2);
    ull X0 = pk2(x0), X1 = pk2(x1), X2 = pk2(x2);
    fma2(a01, w0.x, X0); fma2(a23, w0.y, X0);
    fma2(a01, w1.x, X1); fma2(a23, w1.y, X1);
    fma2(a01, w2.x, X2); fma2(a23, w2.y, X2);
}

// =====================================================================
// persistent RNN kernel: 150 CTAs x 256 threads
// =====================================================================
__global__ void __launch_bounds__(NTH, 1)
rnn_kernel(const float* __restrict__ strokes,
           const int*   __restrict__ chars,
           const int*   __restrict__ lens,
           const float* __restrict__ b0, const float* __restrict__ p0,
           const float* __restrict__ b1, const float* __restrict__ p1,
           const float* __restrict__ b2, const float* __restrict__ p2,
           const float* __restrict__ Watt, const float* __restrict__ batt,
           const float* __restrict__ Wmdn, const float* __restrict__ bmdn,
           float* __restrict__ out)
{
    extern __shared__ float smem[];
    float* s_h   = smem;            // 12800: staged h-vector [k][b]
    float* s_wc  = smem + 12800;    // 2336: staged w-vector [k][b]
    float* s_red = smem + 15136;    // 8*128: stage-4 K-split partials
    float* s_att = smem + 16160;    // 8*76: attention scatter scratch

    const int cta  = blockIdx.x;
    const int tid  = threadIdx.x;
    const int lane = tid & 31;
    const int wib  = tid >> 5;
    const int b    = lane;
    const unsigned FULL = 0xffffffffu;

    // register-resident recurrent state (stable warp<->unit maps)
    float c1reg = 0.f;   // CTAs 0-49: unit = cta*8+wib
    float c2reg = 0.f;   // CTAs 0-49: same unit
    float c3reg = 0.f;   // CTAs 50-149, wib<4: unit = (cta-50)*4+wib
    float kapreg = 0.f;  // CTAs 100-103, warp=batch, lane<10

    for (int t = 0; t < NT; t++) {
        const float* h1prev = (t & 1) ? d_h1b : d_h1a;
        float*       h1cur  = (t & 1) ? d_h1a : d_h1b;
        const float* xp = strokes + (b*NT + t)*3;

        // ======== stage 1: z1+LSTM1 (0-49) | R2 (50-99) | R3 (100-149), 1 warp/unit ========
        if (cta < 50) {
            copy4(s_h,  h1prev, NU*NB);
            copy4(s_wc, d_wT,   NC*NB);
            cpwait();
            int u = cta*8 + wib;
            ull a01 = pk(__ldg(b0+u),      __ldg(b0+NU+u));
            ull a23 = pk(__ldg(b0+2*NU+u), __ldg(b0+3*NU+u));
            const ull2* P = (const ull2*)(d_P0 + u*476);
            accx(a01, a23, P, __ldg(xp), __ldg(xp+1), __ldg(xp+2));
            accseg(a01, a23, P+3,  s_wc, NC, b);
            accseg(a01, a23, P+76, s_h,  NU, b);
            float zi,zf,zg,zo; upk(a01,zi,zf); upk(a23,zg,zo);
            float ig = sigf(zi + __ldg(p0+u)      * c1reg);
            float fg = sigf(zf + __ldg(p0+NU+u)   * c1reg);
            float cn = fg*c1reg + ig*tanhf(zg);
            float og = sigf(zo + __ldg(p0+2*NU+u) * cn);
            c1reg = cn;
            __stcg(&h1cur[u*NB + b], og * tanhf(cn));
        } else if (cta < 100) {
            copy4(s_h, d_h2, NU*NB);
            cpwait();
            int u = (cta-50)*8 + wib;
            ull a01 = pk(__ldg(b1+u),      __ldg(b1+NU+u));
            ull a23 = pk(__ldg(b1+2*NU+u), __ldg(b1+3*NU+u));
            const ull2* P = (const ull2*)(d_P1r + u*403);
            accx(a01, a23, P, __ldg(xp), __ldg(xp+1), __ldg(xp+2));
            accseg(a01, a23, P+3, s_h, NU, b);
            float g0,g1,g2,g3; upk(a01,g0,g1); upk(a23,g2,g3);
            float* dp = d_Z2p + u*128 + b;
            __stcg(dp+0,g0); __stcg(dp+32,g1); __stcg(dp+64,g2); __stcg(dp+96,g3);
        } else {
            copy4(s_h, d_h3, NU*NB);
            cpwait();
            int u = (cta-100)*8 + wib;
            ull a01 = pk(__ldg(b2+u),      __ldg(b2+NU+u));
            ull a23 = pk(__ldg(b2+2*NU+u), __ldg(b2+3*NU+u));
            const ull2* P = (const ull2*)(d_P2r + u*403);
            accx(a01, a23, P, __ldg(xp), __ldg(xp+1), __ldg(xp+2));
            accseg(a01, a23, P+3, s_h, NU, b);
            float g0,g1,g2,g3; upk(a01,g0,g1); upk(a23,g2,g3);
            float* dp = d_R3p + u*128 + b;
            __stcg(dp+0,g0); __stcg(dp+32,g1); __stcg(dp+64,g2); __stcg(dp+96,g3);
        }
        gsync(2*t + 1, cta);

        // ======== stage 2/3: Z2h + attention(w) -> z2+LSTM2 ========
        if (cta < 50) {
            copy4(s_h, h1cur, NU*NB);
            cpwait();
            int u = cta*8 + wib;
            const float* zp = d_Z2p + u*128 + b;
            ull a01 = pk(__ldcg(zp), __ldcg(zp+32));
            ull a23 = pk(__ldcg(zp+64), __ldcg(zp+96));
            accseg(a01, a23, (const ull2*)(d_P1h + u*400), s_h, NU, b);
            // wait for attention w (relaxed, padded flags)
            if (tid < 4) wait_ge(d_flags + (50+tid)*SLOT, (unsigned)(t+1));
            __syncthreads();
            copy4(s_wc, d_wT, NC*NB);
            cpwait();
            accseg(a01, a23, (const ull2*)(d_P1w + u*73), s_wc, NC, b);
            float zi,zf,zg,zo; upk(a01,zi,zf); upk(a23,zg,zo);
            float ig = sigf(zi + __ldg(p1+u)      * c2reg);
            float fg = sigf(zf + __ldg(p1+NU+u)   * c2reg);
            float cn = fg*c2reg + ig*tanhf(zg);
            float og = sigf(zo + __ldg(p1+2*NU+u) * cn);
            c2reg = cn;
            __stcg(&d_h2[u*NB + b], og * tanhf(cn));
            __syncthreads();
            if (tid == 0) st_rel(d_flags + cta*SLOT, (unsigned)(t+1));   // h2 ready
        } else if (cta >= 100 && cta < 104) {
            // attention: warp <-> batch, full K=400
            copy4(s_h, h1cur, NU*NB);
            cpwait();
            int ab = (cta-100)*8 + wib;
            float att = 0.f;
            if (lane < 30) {
                float acc = __ldg(batt + lane);
#pragma unroll 8
                for (int k = 0; k < NU; k++)
                    acc = fmaf(s_h[k*NB + ab], __ldg(Watt + k*30 + lane), acc);
                att = acc;
            }
            float ah = __shfl_sync(FULL, att, (lane < 10) ? lane      : 0);
            float bh = __shfl_sync(FULL, att, (lane < 10) ? lane + 10 : 10);
            float kh = __shfl_sync(FULL, att, (lane < 10) ? lane + 20 : 20);
            float alpha = 0.f, beta = 0.f;
            if (lane < 10) {
                alpha = expf(ah);
                beta  = expf(bh);
                kapreg = kapreg + expf(kh);
            }
            float* sw = s_att + wib*76;
            for (int c = lane; c < NC; c += 32) sw[c] = 0.f;
            __syncwarp();
            int lb = __ldg(lens + ab);
#pragma unroll
            for (int hh = 0; hh < 2; hh++) {
                int uu = lane + hh*32;
                float phi = 0.f;
#pragma unroll
                for (int g = 0; g < NKG; g++) {
                    float ag = __shfl_sync(FULL, alpha,  g);
                    float bg = __shfl_sync(FULL, beta,   g);
                    float kg = __shfl_sync(FULL, kapreg, g);
                    float df = kg - (float)uu;
                    phi = fmaf(ag, expf(-bg*df*df), phi);
                }
                if (uu < NUC && uu < lb) {
                    int c = __ldg(chars + ab*NUC + uu);
                    atomicAdd(&sw[c], phi);
                }
            }
            __syncwarp();
            for (int c = lane; c < NC; c += 32) __stcg(&d_wT[c*NB + ab], sw[c]);
            __syncthreads();
            if (tid == 0) st_rel(d_flags + (50 + cta-100)*SLOT, (unsigned)(t+1));  // w ready
        }

        // ======== stage 4 (CTAs 50-149): z3 = R3p + [w,h2]@P2wh, 2-warp split ========
        if (cta >= 50) {
            if (tid < 54) wait_ge(d_flags + tid*SLOT, (unsigned)(t+1));
            __syncthreads();
            copy4(s_h,  d_h2, NU*NB);
            copy4(s_wc, d_wT, NC*NB);
            cpwait();
            {
                int j = wib >> 1, q = wib & 1;
                int u = (cta-50)*4 + j;
                ull a01 = 0ull, a23 = 0ull;
                const ull2* P = (const ull2*)(d_P2wh + u*473);
                if (q == 0) {
                    accseg(a01, a23, P,    s_wc, NC, b);            // w (73)
                    accseg(a01, a23, P+73, s_h, 164, b);            // h2[0:164)
                } else {
                    accseg(a01, a23, P+237, s_h + 164*NB, 236, b);  // h2[164:400)
                }
                float g0,g1,g2,g3; upk(a01,g0,g1); upk(a23,g2,g3);
                float* rp = s_red + wib*128 + b;
                rp[0]=g0; rp[32]=g1; rp[64]=g2; rp[96]=g3;
            }
            __syncthreads();
            if (wib < 4) {
                int uu = (cta-50)*4 + wib;
                int o4 = uu*128 + b;
                const float* r0 = s_red + (2*wib)*128 + b;
                const float* r1 = s_red + (2*wib+1)*128 + b;
                float zi = __ldcg(d_R3p+o4)    + r0[0]  + r1[0];
                float zf = __ldcg(d_R3p+o4+32) + r0[32] + r1[32];
                float zg = __ldcg(d_R3p+o4+64) + r0[64] + r1[64];
                float zo = __ldcg(d_R3p+o4+96) + r0[96] + r1[96];
                float ig = sigf(zi + __ldg(p2+uu)      * c3reg);
                float fg = sigf(zf + __ldg(p2+NU+uu)   * c3reg);
                float cn = fg*c3reg + ig*tanhf(zg);
                float og = sigf(zo + __ldg(p2+2*NU+uu) * cn);
                c3reg = cn;
                float hv = og * tanhf(cn);
                __stcg(&d_h3[uu*NB + b], hv);
                __stcg(&d_h3all[(t*NU + uu)*NB + b], hv);
            }
        }
        gsync(2*t + 2, cta);
    }

    // ================= MDN head =================
    const int gw = cta*NWARP + wib;
    const int NW = NCTA*NWARP;
    for (int task = gw; task < NB*NT; task += NW) {
        int bb = task / NT;
        int tt = task - bb*NT;
        const float* h3p = d_h3all + (tt*NU)*NB + bb;

        int j0 = lane, j1 = lane + 32, j2 = lane + 64, j3 = lane + 96;
        float a0 = __ldg(bmdn + j0);
        float a1 = __ldg(bmdn + j1);
        float a2 = __ldg(bmdn + j2);
        float a3 = (j3 < NO) ? __ldg(bmdn + j3) : 0.f;
#pragma unroll 4
        for (int k = 0; k < NU; k++) {
            float hv = __ldcg(h3p + k*NB);
            const float* wr = Wmdn + k*NO;
            a0 = fmaf(hv, __ldg(wr + j0), a0);
            a1 = fmaf(hv, __ldg(wr + j1), a1);
            a2 = fmaf(hv, __ldg(wr + j2), a2);
            a3 = fmaf(hv, (j3 < NO) ? __ldg(wr + j3) : 0.f, a3);
        }
        float v = (lane < 20) ? a0 : -INFINITY;
#pragma unroll
        for (int off = 16; off > 0; off >>= 1) v = fmaxf(v, __shfl_xor_sync(FULL, v, off));
        float e = (lane < 20) ? expf(a0 - v) : 0.f;
        float s = e;
#pragma unroll
        for (int off = 16; off > 0; off >>= 1) s += __shfl_xor_sync(FULL, s, off);

        float* op = out + (bb*NT + tt)*NO;
        op[j0] = (lane < 20) ? (e / s) : a0;       // pi | mu1
        op[j1] = (j1 >= 60) ? expf(a1) : a1;       // mu | s1(60-63)
        op[j2] = expf(a2);                         // s1/s2
        if (j3 < NO) {
            float o3;
            if (j3 < 100)      o3 = expf(a3);      // s2
            else if (j3 < 120) o3 = tanhf(a3);     // rho
            else               o3 = sigf(a3);      // eos
            op[j3] = o3;
        }
    }
}

// =====================================================================
// launch
// =====================================================================
extern "C" void kernel_launch(void* const* d_in, const int* in_sizes, int n_in,
                              void* d_out, int out_size)
{
    const float* strokes = (const float*)d_in[0];
    const int*   chars   = (const int*)  d_in[1];
    const int*   lens    = (const int*)  d_in[2];
    const float* Wx0 = (const float*)d_in[3];
    const float* Wh0 = (const float*)d_in[4];
    const float* b0  = (const float*)d_in[5];
    const float* p0  = (const float*)d_in[6];
    const float* Wx1 = (const float*)d_in[7];
    const float* Wh1 = (const float*)d_in[8];
    const float* b1  = (const float*)d_in[9];
    const float* p1  = (const float*)d_in[10];
    const float* Wx2 = (const float*)d_in[11];
    const float* Wh2 = (const float*)d_in[12];
    const float* b2  = (const float*)d_in[13];
    const float* p2  = (const float*)d_in[14];
    const float* Watt = (const float*)d_in[15];
    const float* batt = (const float*)d_in[16];
    const float* Wmdn = (const float*)d_in[17];
    const float* bmdn = (const float*)d_in[18];
    float* out = (float*)d_out;

    static int smem_set = 0;
    const int SMEM_BYTES = (12800 + 2336 + 1024 + 608) * 4;   // 67072
    if (!smem_set) {
        cudaFuncSetAttribute(rnn_kernel, cudaFuncAttributeMaxDynamicSharedMemorySize, SMEM_BYTES);
        smem_set = 1;
    }

    pack_kernel<<<256, 256>>>(Wx0, Wh0, Wx1, Wh1, Wx2, Wh2);
    rnn_kernel<<<NCTA, NTH, SMEM_BYTES>>>(strokes, chars, lens,
                                          b0, p0, b1, p1, b2, p2,
                                          Watt, batt, Wmdn, bmdn, out);
}

// round 11
// speedup vs baseline: 1.6751x; 1.1244x over previous
#include <cuda_runtime.h>
#include <math.h>

#define NB 32      // batch
#define NT 400     // timesteps
#define NU 400     // LSTM units
#define NKG 10     // attention gaussians
#define NC 73      // alphabet
#define NUC 50     // char positions
#define NO 121     // MDN outputs
#define H4 1600    // 4*NU
#define NCTA 150
#define NTH 256
#define NWARP 8
#define SLOT 32    // 128B padding stride for sync words

typedef unsigned long long ull;
#define ull2 ulonglong2

// ---------------- packed weights (gate-interleaved float4 per (u,k)) ----------------
__device__ float4 d_P0  [NU*476];  // layer1: [x(3), w(73), h1(400)]
__device__ float4 d_P1r [NU*403];  // layer2 recurrent: [x(3), h2(400)]
__device__ float4 d_P1h [NU*400];  // layer2 h1 part of Wx1
__device__ float4 d_P1w [NU*73];   // layer2 w part of Wx1
__device__ float4 d_P2r [NU*403];  // layer3 recurrent: [x(3), h3(400)]
__device__ float4 d_P2wh[NU*473];  // layer3 [w(73), h2(400)] part of Wx2

// ---------------- double-buffered state [parity][u*NB+b] ----------------
__device__ float d_h1 [2][NU*NB];
__device__ float d_h2b[2][NU*NB];
__device__ float d_h3b[2][NU*NB];
__device__ float d_wTb[2][NC*NB];
__device__ float d_Z2pb[2][NU*4*NB];
__device__ float d_R3pb[2][NU*4*NB];
__device__ float d_h3all[NT*NU*NB];

// ---------------- versioned flags (monotone step counters, padded) ----------------
__device__ unsigned d_fh1[50*SLOT];    // h1[t] ready per A-CTA      (value t+1)
__device__ unsigned d_fw [4*SLOT];     // w[t] ready per att-CTA
__device__ unsigned d_fh2[50*SLOT];    // h2[t] ready per A-CTA
__device__ unsigned d_fz [50*SLOT];    // Z2p[t] ready per B-CTA
__device__ unsigned d_fr [50*SLOT];    // R3p[t] ready per C-CTA
__device__ unsigned d_fh3[100*SLOT];   // h3[t] ready per S4-CTA (50..149)

// =====================================================================
// pack kernel
// =====================================================================
__global__ void pack_kernel(const float* __restrict__ Wx0, const float* __restrict__ Wh0,
                            const float* __restrict__ Wx1, const float* __restrict__ Wh1,
                            const float* __restrict__ Wx2, const float* __restrict__ Wh2)
{
    int idx = blockIdx.x * blockDim.x + threadIdx.x;
    int str = gridDim.x * blockDim.x;

    for (int e = idx; e < 50*SLOT; e += str) { d_fh1[e]=0u; d_fh2[e]=0u; d_fz[e]=0u; d_fr[e]=0u; }
    for (int e = idx; e < 100*SLOT; e += str) d_fh3[e] = 0u;
    for (int e = idx; e < 4*SLOT; e += str) d_fw[e] = 0u;
    for (int e = idx; e < NU*NB; e += str) {
        d_h1[0][e]=0.f; d_h1[1][e]=0.f; d_h2b[0][e]=0.f; d_h2b[1][e]=0.f;
        d_h3b[0][e]=0.f; d_h3b[1][e]=0.f;
    }
    for (int e = idx; e < NC*NB; e += str) { d_wTb[0][e]=0.f; d_wTb[1][e]=0.f; }

    for (int e = idx; e < NU*476; e += str) {
        int u = e / 476, k = e - u*476;
        const float* s = (k < 76) ? (Wx0 + k*H4) : (Wh0 + (k-76)*H4);
        d_P0[e] = make_float4(s[u], s[NU+u], s[2*NU+u], s[3*NU+u]);
    }
    for (int e = idx; e < NU*403; e += str) {
        int u = e / 403, k = e - u*403;
        const float* s = (k < 3) ? (Wx1 + k*H4) : (Wh1 + (k-3)*H4);
        d_P1r[e] = make_float4(s[u], s[NU+u], s[2*NU+u], s[3*NU+u]);
    }
    for (int e = idx; e < NU*400; e += str) {
        int u = e / 400, k = e - u*400;
        const float* s = Wx1 + (76+k)*H4;
        d_P1h[e] = make_float4(s[u], s[NU+u], s[2*NU+u], s[3*NU+u]);
    }
    for (int e = idx; e < NU*73; e += str) {
        int u = e / 73, k = e - u*73;
        const float* s = Wx1 + (3+k)*H4;
        d_P1w[e] = make_float4(s[u], s[NU+u], s[2*NU+u], s[3*NU+u]);
    }
    for (int e = idx; e < NU*403; e += str) {
        int u = e / 403, k = e - u*403;
        const float* s = (k < 3) ? (Wx2 + k*H4) : (Wh2 + (k-3)*H4);
        d_P2r[e] = make_float4(s[u], s[NU+u], s[2*NU+u], s[3*NU+u]);
    }
    for (int e = idx; e < NU*473; e += str) {
        int u = e / 473, k = e - u*473;
        const float* s = Wx2 + (3+k)*H4;
        d_P2wh[e] = make_float4(s[u], s[NU+u], s[2*NU+u], s[3*NU+u]);
    }
}

// =====================================================================
// helpers
// =====================================================================
__device__ __forceinline__ float sigf(float x) { return 1.f / (1.f + expf(-x)); }

__device__ __forceinline__ ull pk2(float v) {
    ull r; asm("mov.b64 %0, {%1, %1};" : "=l"(r) : "f"(v)); return r;
}
__device__ __forceinline__ ull pk(float lo, float hi) {
    ull r; asm("mov.b64 %0, {%1, %2};" : "=l"(r) : "f"(lo), "f"(hi)); return r;
}
__device__ __forceinline__ void upk(ull v, float& lo, float& hi) {
    asm("mov.b64 {%0, %1}, %2;" : "=f"(lo), "=f"(hi) : "l"(v));
}
__device__ __forceinline__ void fma2(ull& d, ull a, ull b) {
    asm("fma.rn.f32x2 %0, %1, %2, %0;" : "+l"(d) : "l"(a), "l"(b));
}

// weight load: L1 evict_last
__device__ __forceinline__ ull2 ldw(const ull2* p) {
    ull2 r;
    asm("ld.global.nc.L1::evict_last.v2.b64 {%0, %1}, [%2];"
        : "=l"(r.x), "=l"(r.y) : "l"(p));
    return r;
}

__device__ __forceinline__ void st_rel(unsigned* p, unsigned v) {
    asm volatile("{ .reg .u64 a; cvta.to.global.u64 a, %0; st.release.gpu.global.u32 [a], %1; }"
                 :: "l"(p), "r"(v) : "memory");
}
__device__ __forceinline__ unsigned ld_rlx(const unsigned* p) {
    unsigned v;
    asm volatile("{ .reg .u64 a; cvta.to.global.u64 a, %1; ld.relaxed.gpu.global.u32 %0, [a]; }"
                 : "=r"(v) : "l"(p) : "memory");
    return v;
}
// pure spin (no nanosleep)
__device__ __forceinline__ void spin_ge(const unsigned* p, unsigned r) {
    while (ld_rlx(p) < r) { }
}

// staging copy: cp.async.cg — L1 bypass global->shared
__device__ __forceinline__ void copy4(float* dst, const float* src, int nfl)
{
    unsigned base = (unsigned)__cvta_generic_to_shared(dst);
    int n4 = nfl >> 2;
    for (int i = threadIdx.x; i < n4; i += NTH) {
        asm volatile("cp.async.cg.shared.global [%0], [%1], 16;"
                     :: "r"(base + i*16), "l"((const char*)src + i*16) : "memory");
    }
}
__device__ __forceinline__ void cpwait()
{
    asm volatile("cp.async.commit_group;" ::: "memory");
    asm volatile("cp.async.wait_group 0;" ::: "memory");
    __syncthreads();
}

__device__ __forceinline__ void accseg(ull& a01, ull& a23,
                                       const ull2* __restrict__ P,
                                       const float* __restrict__ vs, int K, int b)
{
#pragma unroll 8
    for (int k = 0; k < K; k++) {
        ull hh = pk2(vs[k*NB + b]);
        ull2 w = ldw(P + k);
        fma2(a01, w.x, hh);
        fma2(a23, w.y, hh);
    }
}

__device__ __forceinline__ void accx(ull& a01, ull& a23, const ull2* __restrict__ P,
                                     float x0, float x1, float x2)
{
    ull2 w0 = ldw(P+0), w1 = ldw(P+1), w2 = ldw(P+2);
    ull X0 = pk2(x0), X1 = pk2(x1), X2 = pk2(x2);
    fma2(a01, w0.x, X0); fma2(a23, w0.y, X0);
    fma2(a01, w1.x, X1); fma2(a23, w1.y, X1);
    fma2(a01, w2.x, X2); fma2(a23, w2.y, X2);
}

// =====================================================================
// persistent RNN kernel — pure dataflow, NO global barriers
// =====================================================================
__global__ void __launch_bounds__(NTH, 1)
rnn_kernel(const float* __restrict__ strokes,
           const int*   __restrict__ chars,
           const int*   __restrict__ lens,
           const float* __restrict__ b0, const float* __restrict__ p0,
           const float* __restrict__ b1, const float* __restrict__ p1,
           const float* __restrict__ b2, const float* __restrict__ p2,
           const float* __restrict__ Watt, const float* __restrict__ batt,
           const float* __restrict__ Wmdn, const float* __restrict__ bmdn,
           float* __restrict__ out)
{
    extern __shared__ float smem[];
    float* s_h   = smem;            // 12800: staged h-vector
    float* s_wc  = smem + 12800;    // 2336: staged w-vector
    float* s_red = smem + 15136;    // 8*128: S4 K-split partials
    float* s_att = smem + 16160;    // 8*76: attention scratch

    const int cta  = blockIdx.x;
    const int tid  = threadIdx.x;
    const int lane = tid & 31;
    const int wib  = tid >> 5;
    const int b    = lane;
    const unsigned FULL = 0xffffffffu;

    float c1reg = 0.f, c2reg = 0.f;  // A CTAs: unit = cta*8+wib
    float c3reg = 0.f;               // S4 CTAs (>=50), wib<4: unit = (cta-50)*4+wib
    float kapreg = 0.f;              // att CTAs 100-103

    for (int t = 0; t < NT; t++) {
        const int p = t & 1, q = p ^ 1;
        const unsigned rt = (unsigned)t, rt1 = (unsigned)(t+1);
        const float* xp = strokes + (b*NT + t)*3;

        if (cta < 50) {
            // ================= group A =================
            // ---- S1: needs h1[t-1] (all A) + w[t-1] ----
            if (tid < 50) spin_ge(d_fh1 + tid*SLOT, rt);
            else if (tid < 54) spin_ge(d_fw + (tid-50)*SLOT, rt);
            __syncthreads();
            copy4(s_h,  d_h1[q],  NU*NB);
            copy4(s_wc, d_wTb[q], NC*NB);
            cpwait();
            {
                int u = cta*8 + wib;
                ull a01 = pk(__ldg(b0+u),      __ldg(b0+NU+u));
                ull a23 = pk(__ldg(b0+2*NU+u), __ldg(b0+3*NU+u));
                const ull2* P = (const ull2*)(d_P0 + u*476);
                accx(a01, a23, P, __ldg(xp), __ldg(xp+1), __ldg(xp+2));
                accseg(a01, a23, P+3,  s_wc, NC, b);
                accseg(a01, a23, P+76, s_h,  NU, b);
                float zi,zf,zg,zo; upk(a01,zi,zf); upk(a23,zg,zo);
                float ig = sigf(zi + __ldg(p0+u)      * c1reg);
                float fg = sigf(zf + __ldg(p0+NU+u)   * c1reg);
                float cn = fg*c1reg + ig*tanhf(zg);
                float og = sigf(zo + __ldg(p0+2*NU+u) * cn);
                c1reg = cn;
                __stcg(&d_h1[p][u*NB + b], og * tanhf(cn));
            }
            __syncthreads();
            if (tid == 0) st_rel(d_fh1 + cta*SLOT, rt1);

            // ---- S2/3: Z2h(h1[t]) then +Z2p +w@P1w -> LSTM2 ----
            if (tid < 50) spin_ge(d_fh1 + tid*SLOT, rt1);
            __syncthreads();
            copy4(s_h, d_h1[p], NU*NB);
            cpwait();
            {
                int u = cta*8 + wib;
                ull a01 = 0ull, a23 = 0ull;
                accseg(a01, a23, (const ull2*)(d_P1h + u*400), s_h, NU, b);
                // wait w[t] + Z2p[t] (our units come from B CTA 50+cta)
                if (tid < 4) spin_ge(d_fw + tid*SLOT, rt1);
                if (tid == 4) spin_ge(d_fz + cta*SLOT, rt1);
                __syncthreads();
                copy4(s_wc, d_wTb[p], NC*NB);
                cpwait();
                accseg(a01, a23, (const ull2*)(d_P1w + u*73), s_wc, NC, b);
                const float* zp = d_Z2pb[p] + u*128 + b;
                float zi,zf,zg,zo; upk(a01,zi,zf); upk(a23,zg,zo);
                zi += __ldcg(zp);    zf += __ldcg(zp+32);
                zg += __ldcg(zp+64); zo += __ldcg(zp+96);
                float ig = sigf(zi + __ldg(p1+u)      * c2reg);
                float fg = sigf(zf + __ldg(p1+NU+u)   * c2reg);
                float cn = fg*c2reg + ig*tanhf(zg);
                float og = sigf(zo + __ldg(p1+2*NU+u) * cn);
                c2reg = cn;
                __stcg(&d_h2b[p][u*NB + b], og * tanhf(cn));
            }
            __syncthreads();
            if (tid == 0) st_rel(d_fh2 + cta*SLOT, rt1);
        } else {
            if (cta < 100) {
                // ================= group B: S1-R2 =================
                if (tid < 50) spin_ge(d_fh2 + tid*SLOT, rt);
                __syncthreads();
                copy4(s_h, d_h2b[q], NU*NB);
                cpwait();
                int u = (cta-50)*8 + wib;
                ull a01 = pk(__ldg(b1+u),      __ldg(b1+NU+u));
                ull a23 = pk(__ldg(b1+2*NU+u), __ldg(b1+3*NU+u));
                const ull2* P = (const ull2*)(d_P1r + u*403);
                accx(a01, a23, P, __ldg(xp), __ldg(xp+1), __ldg(xp+2));
                accseg(a01, a23, P+3, s_h, NU, b);
                float g0,g1,g2,g3; upk(a01,g0,g1); upk(a23,g2,g3);
                float* dp = d_Z2pb[p] + u*128 + b;
                __stcg(dp+0,g0); __stcg(dp+32,g1); __stcg(dp+64,g2); __stcg(dp+96,g3);
                __syncthreads();
                if (tid == 0) st_rel(d_fz + (cta-50)*SLOT, rt1);
            } else {
                // ================= group C: S1-R3 =================
                if (tid < 100) spin_ge(d_fh3 + tid*SLOT, rt);
                __syncthreads();
                copy4(s_h, d_h3b[q], NU*NB);
                cpwait();
                int u = (cta-100)*8 + wib;
                ull a01 = pk(__ldg(b2+u),      __ldg(b2+NU+u));
                ull a23 = pk(__ldg(b2+2*NU+u), __ldg(b2+3*NU+u));
                const ull2* P = (const ull2*)(d_P2r + u*403);
                accx(a01, a23, P, __ldg(xp), __ldg(xp+1), __ldg(xp+2));
                accseg(a01, a23, P+3, s_h, NU, b);
                float g0,g1,g2,g3; upk(a01,g0,g1); upk(a23,g2,g3);
                float* dp = d_R3pb[p] + u*128 + b;
                __stcg(dp+0,g0); __stcg(dp+32,g1); __stcg(dp+64,g2); __stcg(dp+96,g3);
                __syncthreads();
                if (tid == 0) st_rel(d_fr + (cta-100)*SLOT, rt1);

                // ---- attention (CTAs 100-103) ----
                if (cta < 104) {
                    if (tid < 50) spin_ge(d_fh1 + tid*SLOT, rt1);
                    __syncthreads();
                    copy4(s_h, d_h1[p], NU*NB);
                    cpwait();
                    int ab = (cta-100)*8 + wib;
                    float att = 0.f;
                    if (lane < 30) {
                        float acc = __ldg(batt + lane);
#pragma unroll 8
                        for (int k = 0; k < NU; k++)
                            acc = fmaf(s_h[k*NB + ab], __ldg(Watt + k*30 + lane), acc);
                        att = acc;
                    }
                    float ah = __shfl_sync(FULL, att, (lane < 10) ? lane      : 0);
                    float bh = __shfl_sync(FULL, att, (lane < 10) ? lane + 10 : 10);
                    float kh = __shfl_sync(FULL, att, (lane < 10) ? lane + 20 : 20);
                    float alpha = 0.f, beta = 0.f;
                    if (lane < 10) {
                        alpha = expf(ah);
                        beta  = expf(bh);
                        kapreg = kapreg + expf(kh);
                    }
                    float* sw = s_att + wib*76;
                    for (int c = lane; c < NC; c += 32) sw[c] = 0.f;
                    __syncwarp();
                    int lb = __ldg(lens + ab);
#pragma unroll
                    for (int hh = 0; hh < 2; hh++) {
                        int uu = lane + hh*32;
                        float phi = 0.f;
#pragma unroll
                        for (int g = 0; g < NKG; g++) {
                            float ag = __shfl_sync(FULL, alpha,  g);
                            float bg = __shfl_sync(FULL, beta,   g);
                            float kg = __shfl_sync(FULL, kapreg, g);
                            float df = kg - (float)uu;
                            phi = fmaf(ag, expf(-bg*df*df), phi);
                        }
                        if (uu < NUC && uu < lb) {
                            int c = __ldg(chars + ab*NUC + uu);
                            atomicAdd(&sw[c], phi);
                        }
                    }
                    __syncwarp();
                    for (int c = lane; c < NC; c += 32) __stcg(&d_wTb[p][c*NB + ab], sw[c]);
                    __syncthreads();
                    if (tid == 0) st_rel(d_fw + (cta-100)*SLOT, rt1);
                }
            }

            // ================= common S4 (CTAs 50-149) =================
            if (tid < 50) spin_ge(d_fh2 + tid*SLOT, rt1);
            else if (tid < 54) spin_ge(d_fw + (tid-50)*SLOT, rt1);
            else if (tid == 54) spin_ge(d_fr + ((cta-50)>>1)*SLOT, rt1);
            __syncthreads();
            copy4(s_h,  d_h2b[p], NU*NB);
            copy4(s_wc, d_wTb[p], NC*NB);
            cpwait();
            {
                int j = wib >> 1, hq = wib & 1;
                int u = (cta-50)*4 + j;
                ull a01 = 0ull, a23 = 0ull;
                const ull2* P = (const ull2*)(d_P2wh + u*473);
                if (hq == 0) {
                    accseg(a01, a23, P,    s_wc, NC, b);
                    accseg(a01, a23, P+73, s_h, 164, b);
                } else {
                    accseg(a01, a23, P+237, s_h + 164*NB, 236, b);
                }
                float g0,g1,g2,g3; upk(a01,g0,g1); upk(a23,g2,g3);
                float* rp = s_red + wib*128 + b;
                rp[0]=g0; rp[32]=g1; rp[64]=g2; rp[96]=g3;
            }
            __syncthreads();
            if (wib < 4) {
                int uu = (cta-50)*4 + wib;
                int o4 = uu*128 + b;
                const float* rr = d_R3pb[p];
                const float* r0 = s_red + (2*wib)*128 + b;
                const float* r1 = s_red + (2*wib+1)*128 + b;
                float zi = __ldcg(rr+o4)    + r0[0]  + r1[0];
                float zf = __ldcg(rr+o4+32) + r0[32] + r1[32];
                float zg = __ldcg(rr+o4+64) + r0[64] + r1[64];
                float zo = __ldcg(rr+o4+96) + r0[96] + r1[96];
                float ig = sigf(zi + __ldg(p2+uu)      * c3reg);
                float fg = sigf(zf + __ldg(p2+NU+uu)   * c3reg);
                float cn = fg*c3reg + ig*tanhf(zg);
                float og = sigf(zo + __ldg(p2+2*NU+uu) * cn);
                c3reg = cn;
                float hv = og * tanhf(cn);
                __stcg(&d_h3b[p][uu*NB + b], hv);
                __stcg(&d_h3all[(t*NU + uu)*NB + b], hv);
            }
            __syncthreads();
            if (tid == 0) st_rel(d_fh3 + (cta-50)*SLOT, rt1);
        }
    }

    // ================= MDN head (after all h3 written) =================
    if (tid < 100) spin_ge(d_fh3 + tid*SLOT, (unsigned)NT);
    __syncthreads();

    const int gw = cta*NWARP + wib;
    const int NW = NCTA*NWARP;
    for (int task = gw; task < NB*NT; task += NW) {
        int bb = task / NT;
        int tt = task - bb*NT;
        const float* h3p = d_h3all + (tt*NU)*NB + bb;

        int j0 = lane, j1 = lane + 32, j2 = lane + 64, j3 = lane + 96;
        float a0 = __ldg(bmdn + j0);
        float a1 = __ldg(bmdn + j1);
        float a2 = __ldg(bmdn + j2);
        float a3 = (j3 < NO) ? __ldg(bmdn + j3) : 0.f;
#pragma unroll 4
        for (int k = 0; k < NU; k++) {
            float hv = __ldcg(h3p + k*NB);
            const float* wr = Wmdn + k*NO;
            a0 = fmaf(hv, __ldg(wr + j0), a0);
            a1 = fmaf(hv, __ldg(wr + j1), a1);
            a2 = fmaf(hv, __ldg(wr + j2), a2);
            a3 = fmaf(hv, (j3 < NO) ? __ldg(wr + j3) : 0.f, a3);
        }
        float v = (lane < 20) ? a0 : -INFINITY;
#pragma unroll
        for (int off = 16; off > 0; off >>= 1) v = fmaxf(v, __shfl_xor_sync(FULL, v, off));
        float e = (lane < 20) ? expf(a0 - v) : 0.f;
        float s = e;
#pragma unroll
        for (int off = 16; off > 0; off >>= 1) s += __shfl_xor_sync(FULL, s, off);

        float* op = out + (bb*NT + tt)*NO;
        op[j0] = (lane < 20) ? (e / s) : a0;       // pi | mu1
        op[j1] = (j1 >= 60) ? expf(a1) : a1;       // mu | s1(60-63)
        op[j2] = expf(a2);                         // s1/s2
        if (j3 < NO) {
            float o3;
            if (j3 < 100)      o3 = expf(a3);      // s2
            else if (j3 < 120) o3 = tanhf(a3);     // rho
            else               o3 = sigf(a3);      // eos
            op[j3] = o3;
        }
    }
}

// =====================================================================
// launch
// =====================================================================
extern "C" void kernel_launch(void* const* d_in, const int* in_sizes, int n_in,
                              void* d_out, int out_size)
{
    const float* strokes = (const float*)d_in[0];
    const int*   chars   = (const int*)  d_in[1];
    const int*   lens    = (const int*)  d_in[2];
    const float* Wx0 = (const float*)d_in[3];
    const float* Wh0 = (const float*)d_in[4];
    const float* b0  = (const float*)d_in[5];
    const float* p0  = (const float*)d_in[6];
    const float* Wx1 = (const float*)d_in[7];
    const float* Wh1 = (const float*)d_in[8];
    const float* b1  = (const float*)d_in[9];
    const float* p1  = (const float*)d_in[10];
    const float* Wx2 = (const float*)d_in[11];
    const float* Wh2 = (const float*)d_in[12];
    const float* b2  = (const float*)d_in[13];
    const float* p2  = (const float*)d_in[14];
    const float* Watt = (const float*)d_in[15];
    const float* batt = (const float*)d_in[16];
    const float* Wmdn = (const float*)d_in[17];
    const float* bmdn = (const float*)d_in[18];
    float* out = (float*)d_out;

    static int smem_set = 0;
    const int SMEM_BYTES = (12800 + 2336 + 1024 + 608) * 4;   // 67072
    if (!smem_set) {
        cudaFuncSetAttribute(rnn_kernel, cudaFuncAttributeMaxDynamicSharedMemorySize, SMEM_BYTES);
        smem_set = 1;
    }

    pack_kernel<<<256, 256>>>(Wx0, Wh0, Wx1, Wh1, Wx2, Wh2);
    rnn_kernel<<<NCTA, NTH, SMEM_BYTES>>>(strokes, chars, lens,
                                          b0, p0, b1, p1, b2, p2,
                                          Watt, batt, Wmdn, bmdn, out);
}

// round 12
// speedup vs baseline: 2.3555x; 1.4062x over previous
#include <cuda_runtime.h>
#include <math.h>

#define NB 32      // batch
#define NT 400     // timesteps
#define NU 400     // LSTM units
#define NKG 10     // attention gaussians
#define NC 73      // alphabet
#define NUC 50     // char positions
#define NO 121     // MDN outputs
#define H4 1600    // 4*NU
#define NCTA 150
#define NTH 256
#define NWARP 8
#define SLOT 32    // 128B padding stride for sync words

// smem layout (float offsets)
#define OFF_H    0        // 12800: staged h-vector
#define OFF_WC   12800    // 2336: staged w-vector
#define OFF_RED  15136    // 1024: S4 K-split partials
#define OFF_ATT  16160    // 608: attention scratch
#define OFF_W    16768    // weights region
// group A: P0 slice (8*476*4), P1h slice (8*400*4), P1w slice (8*73*4)
#define OFF_P0   16768
#define OFF_P1H  32000
#define OFF_P1W  44800    // end A: 47136 floats
// group S4 (50-149): Pr slice (8*403*4), P2wh slice (4*473*4), Watt (12000)
#define OFF_PR   16768
#define OFF_P2WH 29664
#define OFF_WATT 37232    // end att: 49232 floats
#define SMEM_FLOATS 49232
#define SMEM_BYTES (SMEM_FLOATS*4)   // 196928

typedef unsigned long long ull;
#define ull2 ulonglong2

// ---------------- packed weights (gate-interleaved float4 per (u,k)) ----------------
__device__ float4 d_P0  [NU*476];
__device__ float4 d_P1r [NU*403];
__device__ float4 d_P1h [NU*400];
__device__ float4 d_P1w [NU*73];
__device__ float4 d_P2r [NU*403];
__device__ float4 d_P2wh[NU*473];

// ---------------- double-buffered state [parity][u*NB+b] ----------------
__device__ float d_h1 [2][NU*NB];
__device__ float d_h2b[2][NU*NB];
__device__ float d_h3b[2][NU*NB];
__device__ float d_wTb[2][NC*NB];
__device__ float d_Z2pb[2][NU*4*NB];
__device__ float d_R3pb[2][NU*4*NB];
__device__ float d_h3all[NT*NU*NB];

// ---------------- versioned flags ----------------
__device__ unsigned d_fh1[50*SLOT];
__device__ unsigned d_fw [4*SLOT];
__device__ unsigned d_fh2[50*SLOT];
__device__ unsigned d_fz [50*SLOT];
__device__ unsigned d_fr [50*SLOT];
__device__ unsigned d_fh3[100*SLOT];

// =====================================================================
// pack kernel
// =====================================================================
__global__ void pack_kernel(const float* __restrict__ Wx0, const float* __restrict__ Wh0,
                            const float* __restrict__ Wx1, const float* __restrict__ Wh1,
                            const float* __restrict__ Wx2, const float* __restrict__ Wh2)
{
    int idx = blockIdx.x * blockDim.x + threadIdx.x;
    int str = gridDim.x * blockDim.x;

    for (int e = idx; e < 50*SLOT; e += str) { d_fh1[e]=0u; d_fh2[e]=0u; d_fz[e]=0u; d_fr[e]=0u; }
    for (int e = idx; e < 100*SLOT; e += str) d_fh3[e] = 0u;
    for (int e = idx; e < 4*SLOT; e += str) d_fw[e] = 0u;
    for (int e = idx; e < NU*NB; e += str) {
        d_h1[0][e]=0.f; d_h1[1][e]=0.f; d_h2b[0][e]=0.f; d_h2b[1][e]=0.f;
        d_h3b[0][e]=0.f; d_h3b[1][e]=0.f;
    }
    for (int e = idx; e < NC*NB; e += str) { d_wTb[0][e]=0.f; d_wTb[1][e]=0.f; }

    for (int e = idx; e < NU*476; e += str) {
        int u = e / 476, k = e - u*476;
        const float* s = (k < 76) ? (Wx0 + k*H4) : (Wh0 + (k-76)*H4);
        d_P0[e] = make_float4(s[u], s[NU+u], s[2*NU+u], s[3*NU+u]);
    }
    for (int e = idx; e < NU*403; e += str) {
        int u = e / 403, k = e - u*403;
        const float* s = (k < 3) ? (Wx1 + k*H4) : (Wh1 + (k-3)*H4);
        d_P1r[e] = make_float4(s[u], s[NU+u], s[2*NU+u], s[3*NU+u]);
    }
    for (int e = idx; e < NU*400; e += str) {
        int u = e / 400, k = e - u*400;
        const float* s = Wx1 + (76+k)*H4;
        d_P1h[e] = make_float4(s[u], s[NU+u], s[2*NU+u], s[3*NU+u]);
    }
    for (int e = idx; e < NU*73; e += str) {
        int u = e / 73, k = e - u*73;
        const float* s = Wx1 + (3+k)*H4;
        d_P1w[e] = make_float4(s[u], s[NU+u], s[2*NU+u], s[3*NU+u]);
    }
    for (int e = idx; e < NU*403; e += str) {
        int u = e / 403, k = e - u*403;
        const float* s = (k < 3) ? (Wx2 + k*H4) : (Wh2 + (k-3)*H4);
        d_P2r[e] = make_float4(s[u], s[NU+u], s[2*NU+u], s[3*NU+u]);
    }
    for (int e = idx; e < NU*473; e += str) {
        int u = e / 473, k = e - u*473;
        const float* s = Wx2 + (3+k)*H4;
        d_P2wh[e] = make_float4(s[u], s[NU+u], s[2*NU+u], s[3*NU+u]);
    }
}

// =====================================================================
// helpers
// =====================================================================
__device__ __forceinline__ float sigf(float x) { return 1.f / (1.f + expf(-x)); }

__device__ __forceinline__ ull pk2(float v) {
    ull r; asm("mov.b64 %0, {%1, %1};" : "=l"(r) : "f"(v)); return r;
}
__device__ __forceinline__ ull pk(float lo, float hi) {
    ull r; asm("mov.b64 %0, {%1, %2};" : "=l"(r) : "f"(lo), "f"(hi)); return r;
}
__device__ __forceinline__ void upk(ull v, float& lo, float& hi) {
    asm("mov.b64 {%0, %1}, %2;" : "=f"(lo), "=f"(hi) : "l"(v));
}
__device__ __forceinline__ void fma2(ull& d, ull a, ull b) {
    asm("fma.rn.f32x2 %0, %1, %2, %0;" : "+l"(d) : "l"(a), "l"(b));
}

__device__ __forceinline__ void st_rel(unsigned* p, unsigned v) {
    asm volatile("{ .reg .u64 a; cvta.to.global.u64 a, %0; st.release.gpu.global.u32 [a], %1; }"
                 :: "l"(p), "r"(v) : "memory");
}
__device__ __forceinline__ unsigned ld_rlx(const unsigned* p) {
    unsigned v;
    asm volatile("{ .reg .u64 a; cvta.to.global.u64 a, %1; ld.relaxed.gpu.global.u32 %0, [a]; }"
                 : "=r"(v) : "l"(p) : "memory");
    return v;
}
__device__ __forceinline__ void spin_ge(const unsigned* p, unsigned r) {
    while (ld_rlx(p) < r) { }
}

// staging copy: cp.async.cg — L1 bypass global->shared
__device__ __forceinline__ void copy4(float* dst, const float* src, int nfl)
{
    unsigned base = (unsigned)__cvta_generic_to_shared(dst);
    int n4 = nfl >> 2;
    for (int i = threadIdx.x; i < n4; i += NTH) {
        asm volatile("cp.async.cg.shared.global [%0], [%1], 16;"
                     :: "r"(base + i*16), "l"((const char*)src + i*16) : "memory");
    }
}
__device__ __forceinline__ void cpwait()
{
    asm volatile("cp.async.commit_group;" ::: "memory");
    asm volatile("cp.async.wait_group 0;" ::: "memory");
    __syncthreads();
}

// gate accumulation: weights AND state from SMEM (explicit LDS), unroll 8
// wbyte: smem byte addr of weight stream (ull2 per k); vbyte: smem byte addr of state row 0
__device__ __forceinline__ void accsegS(ull& a01, ull& a23,
                                        unsigned wbyte, unsigned vbyte, int K, int b)
{
    unsigned va = vbyte + b*4;
#pragma unroll 8
    for (int k = 0; k < K; k++) {
        float hv;
        asm("ld.shared.b32 %0, [%1];" : "=f"(hv) : "r"(va + k*(NB*4)));
        ull wx, wy;
        asm("ld.shared.v2.b64 {%0, %1}, [%2];" : "=l"(wx), "=l"(wy) : "r"(wbyte + k*16));
        ull hh = pk2(hv);
        fma2(a01, wx, hh);
        fma2(a23, wy, hh);
    }
}

__device__ __forceinline__ void accxS(ull& a01, ull& a23, unsigned wbyte,
                                      float x0, float x1, float x2)
{
    ull w0x,w0y,w1x,w1y,w2x,w2y;
    asm("ld.shared.v2.b64 {%0, %1}, [%2];" : "=l"(w0x), "=l"(w0y) : "r"(wbyte));
    asm("ld.shared.v2.b64 {%0, %1}, [%2];" : "=l"(w1x), "=l"(w1y) : "r"(wbyte+16));
    asm("ld.shared.v2.b64 {%0, %1}, [%2];" : "=l"(w2x), "=l"(w2y) : "r"(wbyte+32));
    ull X0 = pk2(x0), X1 = pk2(x1), X2 = pk2(x2);
    fma2(a01, w0x, X0); fma2(a23, w0y, X0);
    fma2(a01, w1x, X1); fma2(a23, w1y, X1);
    fma2(a01, w2x, X2); fma2(a23, w2y, X2);
}

// =====================================================================
// persistent RNN kernel — dataflow, weights resident in SMEM
// =====================================================================
__global__ void __launch_bounds__(NTH, 1)
rnn_kernel(const float* __restrict__ strokes,
           const int*   __restrict__ chars,
           const int*   __restrict__ lens,
           const float* __restrict__ b0, const float* __restrict__ p0,
           const float* __restrict__ b1, const float* __restrict__ p1,
           const float* __restrict__ b2, const float* __restrict__ p2,
           const float* __restrict__ Watt, const float* __restrict__ batt,
           const float* __restrict__ Wmdn, const float* __restrict__ bmdn,
           float* __restrict__ out)
{
    extern __shared__ float smem[];
    float* s_h   = smem + OFF_H;
    float* s_wc  = smem + OFF_WC;
    float* s_red = smem + OFF_RED;
    float* s_att = smem + OFF_ATT;
    float* s_watt = smem + OFF_WATT;
    const unsigned sb = (unsigned)__cvta_generic_to_shared(smem);

    const int cta  = blockIdx.x;
    const int tid  = threadIdx.x;
    const int lane = tid & 31;
    const int wib  = tid >> 5;
    const int b    = lane;
    const unsigned FULL = 0xffffffffu;

    // ---- preload weight slices into smem (once) ----
    if (cta < 50) {
        copy4(smem + OFF_P0,  (const float*)(d_P0  + cta*8*476), 8*476*4);
        copy4(smem + OFF_P1H, (const float*)(d_P1h + cta*8*400), 8*400*4);
        copy4(smem + OFF_P1W, (const float*)(d_P1w + cta*8*73),  8*73*4);
    } else {
        const float4* prsrc = (cta < 100) ? (d_P1r + (cta-50)*8*403)
                                          : (d_P2r + (cta-100)*8*403);
        copy4(smem + OFF_PR,   (const float*)prsrc, 8*403*4);
        copy4(smem + OFF_P2WH, (const float*)(d_P2wh + (cta-50)*4*473), 4*473*4);
        if (cta >= 100 && cta < 104)
            copy4(s_watt, Watt, NU*30);
    }
    cpwait();

    float c1reg = 0.f, c2reg = 0.f;  // A CTAs: unit = cta*8+wib
    float c3reg = 0.f;               // S4 CTAs, wib<4: unit = (cta-50)*4+wib
    float kapreg = 0.f;              // att CTAs 100-103

    for (int t = 0; t < NT; t++) {
        const int p = t & 1, q = p ^ 1;
        const unsigned rt = (unsigned)t, rt1 = (unsigned)(t+1);
        const float* xp = strokes + (b*NT + t)*3;

        if (cta < 50) {
            // ================= group A =================
            // ---- S1 ----
            if (tid < 50) spin_ge(d_fh1 + tid*SLOT, rt);
            else if (tid < 54) spin_ge(d_fw + (tid-50)*SLOT, rt);
            __syncthreads();
            copy4(s_h,  d_h1[q],  NU*NB);
            copy4(s_wc, d_wTb[q], NC*NB);
            cpwait();
            {
                int u = cta*8 + wib;
                unsigned wb = sb + (OFF_P0 + wib*476*4)*4;
                ull a01 = pk(__ldg(b0+u),      __ldg(b0+NU+u));
                ull a23 = pk(__ldg(b0+2*NU+u), __ldg(b0+3*NU+u));
                accxS(a01, a23, wb, __ldg(xp), __ldg(xp+1), __ldg(xp+2));
                accsegS(a01, a23, wb + 3*16,  sb + OFF_WC*4, NC, b);
                accsegS(a01, a23, wb + 76*16, sb + OFF_H*4,  NU, b);
                float zi,zf,zg,zo; upk(a01,zi,zf); upk(a23,zg,zo);
                float ig = sigf(zi + __ldg(p0+u)      * c1reg);
                float fg = sigf(zf + __ldg(p0+NU+u)   * c1reg);
                float cn = fg*c1reg + ig*tanhf(zg);
                float og = sigf(zo + __ldg(p0+2*NU+u) * cn);
                c1reg = cn;
                __stcg(&d_h1[p][u*NB + b], og * tanhf(cn));
            }
            __syncthreads();
            if (tid == 0) st_rel(d_fh1 + cta*SLOT, rt1);

            // ---- S2/3 ----
            if (tid < 50) spin_ge(d_fh1 + tid*SLOT, rt1);
            __syncthreads();
            copy4(s_h, d_h1[p], NU*NB);
            cpwait();
            {
                int u = cta*8 + wib;
                ull a01 = 0ull, a23 = 0ull;
                accsegS(a01, a23, sb + (OFF_P1H + wib*400*4)*4, sb + OFF_H*4, NU, b);
                if (tid < 4) spin_ge(d_fw + tid*SLOT, rt1);
                if (tid == 4) spin_ge(d_fz + cta*SLOT, rt1);
                __syncthreads();
                copy4(s_wc, d_wTb[p], NC*NB);
                cpwait();
                accsegS(a01, a23, sb + (OFF_P1W + wib*73*4)*4, sb + OFF_WC*4, NC, b);
                const float* zp = d_Z2pb[p] + u*128 + b;
                float zi,zf,zg,zo; upk(a01,zi,zf); upk(a23,zg,zo);
                zi += __ldcg(zp);    zf += __ldcg(zp+32);
                zg += __ldcg(zp+64); zo += __ldcg(zp+96);
                float ig = sigf(zi + __ldg(p1+u)      * c2reg);
                float fg = sigf(zf + __ldg(p1+NU+u)   * c2reg);
                float cn = fg*c2reg + ig*tanhf(zg);
                float og = sigf(zo + __ldg(p1+2*NU+u) * cn);
                c2reg = cn;
                __stcg(&d_h2b[p][u*NB + b], og * tanhf(cn));
            }
            __syncthreads();
            if (tid == 0) st_rel(d_fh2 + cta*SLOT, rt1);
        } else {
            if (cta < 100) {
                // ================= group B: S1-R2 =================
                if (tid < 50) spin_ge(d_fh2 + tid*SLOT, rt);
                __syncthreads();
                copy4(s_h, d_h2b[q], NU*NB);
                cpwait();
                int u = (cta-50)*8 + wib;
                unsigned wb = sb + (OFF_PR + wib*403*4)*4;
                ull a01 = pk(__ldg(b1+u),      __ldg(b1+NU+u));
                ull a23 = pk(__ldg(b1+2*NU+u), __ldg(b1+3*NU+u));
                accxS(a01, a23, wb, __ldg(xp), __ldg(xp+1), __ldg(xp+2));
                accsegS(a01, a23, wb + 3*16, sb + OFF_H*4, NU, b);
                float g0,g1,g2,g3; upk(a01,g0,g1); upk(a23,g2,g3);
                float* dp = d_Z2pb[p] + u*128 + b;
                __stcg(dp+0,g0); __stcg(dp+32,g1); __stcg(dp+64,g2); __stcg(dp+96,g3);
                __syncthreads();
                if (tid == 0) st_rel(d_fz + (cta-50)*SLOT, rt1);
            } else {
                // ================= group C: S1-R3 =================
                if (tid < 100) spin_ge(d_fh3 + tid*SLOT, rt);
                __syncthreads();
                copy4(s_h, d_h3b[q], NU*NB);
                cpwait();
                int u = (cta-100)*8 + wib;
                unsigned wb = sb + (OFF_PR + wib*403*4)*4;
                ull a01 = pk(__ldg(b2+u),      __ldg(b2+NU+u));
                ull a23 = pk(__ldg(b2+2*NU+u), __ldg(b2+3*NU+u));
                accxS(a01, a23, wb, __ldg(xp), __ldg(xp+1), __ldg(xp+2));
                accsegS(a01, a23, wb + 3*16, sb + OFF_H*4, NU, b);
                float g0,g1,g2,g3; upk(a01,g0,g1); upk(a23,g2,g3);
                float* dp = d_R3pb[p] + u*128 + b;
                __stcg(dp+0,g0); __stcg(dp+32,g1); __stcg(dp+64,g2); __stcg(dp+96,g3);
                __syncthreads();
                if (tid == 0) st_rel(d_fr + (cta-100)*SLOT, rt1);

                // ---- attention (CTAs 100-103) ----
                if (cta < 104) {
                    if (tid < 50) spin_ge(d_fh1 + tid*SLOT, rt1);
                    __syncthreads();
                    copy4(s_h, d_h1[p], NU*NB);
                    cpwait();
                    int ab = (cta-100)*8 + wib;
                    float att = 0.f;
                    if (lane < 30) {
                        float acc = __ldg(batt + lane);
#pragma unroll 8
                        for (int k = 0; k < NU; k++)
                            acc = fmaf(s_h[k*NB + ab], s_watt[k*30 + lane], acc);
                        att = acc;
                    }
                    float ah = __shfl_sync(FULL, att, (lane < 10) ? lane      : 0);
                    float bh = __shfl_sync(FULL, att, (lane < 10) ? lane + 10 : 10);
                    float kh = __shfl_sync(FULL, att, (lane < 10) ? lane + 20 : 20);
                    float alpha = 0.f, beta = 0.f;
                    if (lane < 10) {
                        alpha = expf(ah);
                        beta  = expf(bh);
                        kapreg = kapreg + expf(kh);
                    }
                    float* sw = s_att + wib*76;
                    for (int c = lane; c < NC; c += 32) sw[c] = 0.f;
                    __syncwarp();
                    int lb = __ldg(lens + ab);
#pragma unroll
                    for (int hh = 0; hh < 2; hh++) {
                        int uu = lane + hh*32;
                        float phi = 0.f;
#pragma unroll
                        for (int g = 0; g < NKG; g++) {
                            float ag = __shfl_sync(FULL, alpha,  g);
                            float bg = __shfl_sync(FULL, beta,   g);
                            float kg = __shfl_sync(FULL, kapreg, g);
                            float df = kg - (float)uu;
                            phi = fmaf(ag, expf(-bg*df*df), phi);
                        }
                        if (uu < NUC && uu < lb) {
                            int c = __ldg(chars + ab*NUC + uu);
                            atomicAdd(&sw[c], phi);
                        }
                    }
                    __syncwarp();
                    for (int c = lane; c < NC; c += 32) __stcg(&d_wTb[p][c*NB + ab], sw[c]);
                    __syncthreads();
                    if (tid == 0) st_rel(d_fw + (cta-100)*SLOT, rt1);
                }
            }

            // ================= common S4 (CTAs 50-149) =================
            if (tid < 50) spin_ge(d_fh2 + tid*SLOT, rt1);
            else if (tid < 54) spin_ge(d_fw + (tid-50)*SLOT, rt1);
            else if (tid == 54) spin_ge(d_fr + ((cta-50)>>1)*SLOT, rt1);
            __syncthreads();
            copy4(s_h,  d_h2b[p], NU*NB);
            copy4(s_wc, d_wTb[p], NC*NB);
            cpwait();
            {
                int j = wib >> 1, hq = wib & 1;
                ull a01 = 0ull, a23 = 0ull;
                unsigned wb = sb + (OFF_P2WH + j*473*4)*4;
                if (hq == 0) {
                    accsegS(a01, a23, wb,         sb + OFF_WC*4, NC, b);
                    accsegS(a01, a23, wb + 73*16, sb + OFF_H*4, 164, b);
                } else {
                    accsegS(a01, a23, wb + 237*16, sb + (OFF_H + 164*NB)*4, 236, b);
                }
                float g0,g1,g2,g3; upk(a01,g0,g1); upk(a23,g2,g3);
                float* rp = s_red + wib*128 + b;
                rp[0]=g0; rp[32]=g1; rp[64]=g2; rp[96]=g3;
            }
            __syncthreads();
            if (wib < 4) {
                int uu = (cta-50)*4 + wib;
                int o4 = uu*128 + b;
                const float* rr = d_R3pb[p];
                const float* r0 = s_red + (2*wib)*128 + b;
                const float* r1 = s_red + (2*wib+1)*128 + b;
                float zi = __ldcg(rr+o4)    + r0[0]  + r1[0];
                float zf = __ldcg(rr+o4+32) + r0[32] + r1[32];
                float zg = __ldcg(rr+o4+64) + r0[64] + r1[64];
                float zo = __ldcg(rr+o4+96) + r0[96] + r1[96];
                float ig = sigf(zi + __ldg(p2+uu)      * c3reg);
                float fg = sigf(zf + __ldg(p2+NU+uu)   * c3reg);
                float cn = fg*c3reg + ig*tanhf(zg);
                float og = sigf(zo + __ldg(p2+2*NU+uu) * cn);
                c3reg = cn;
                float hv = og * tanhf(cn);
                __stcg(&d_h3b[p][uu*NB + b], hv);
                __stcg(&d_h3all[(t*NU + uu)*NB + b], hv);
            }
            __syncthreads();
            if (tid == 0) st_rel(d_fh3 + (cta-50)*SLOT, rt1);
        }
    }

    // ================= MDN head =================
    if (tid < 100) spin_ge(d_fh3 + tid*SLOT, (unsigned)NT);
    __syncthreads();

    const int gw = cta*NWARP + wib;
    const int NW = NCTA*NWARP;
    for (int task = gw; task < NB*NT; task += NW) {
        int bb = task / NT;
        int tt = task - bb*NT;
        const float* h3p = d_h3all + (tt*NU)*NB + bb;

        int j0 = lane, j1 = lane + 32, j2 = lane + 64, j3 = lane + 96;
        float a0 = __ldg(bmdn + j0);
        float a1 = __ldg(bmdn + j1);
        float a2 = __ldg(bmdn + j2);
        float a3 = (j3 < NO) ? __ldg(bmdn + j3) : 0.f;
#pragma unroll 4
        for (int k = 0; k < NU; k++) {
            float hv = __ldcg(h3p + k*NB);
            const float* wr = Wmdn + k*NO;
            a0 = fmaf(hv, __ldg(wr + j0), a0);
            a1 = fmaf(hv, __ldg(wr + j1), a1);
            a2 = fmaf(hv, __ldg(wr + j2), a2);
            a3 = fmaf(hv, (j3 < NO) ? __ldg(wr + j3) : 0.f, a3);
        }
        float v = (lane < 20) ? a0 : -INFINITY;
#pragma unroll
        for (int off = 16; off > 0; off >>= 1) v = fmaxf(v, __shfl_xor_sync(FULL, v, off));
        float e = (lane < 20) ? expf(a0 - v) : 0.f;
        float s = e;
#pragma unroll
        for (int off = 16; off > 0; off >>= 1) s += __shfl_xor_sync(FULL, s, off);

        float* op = out + (bb*NT + tt)*NO;
        op[j0] = (lane < 20) ? (e / s) : a0;       // pi | mu1
        op[j1] = (j1 >= 60) ? expf(a1) : a1;       // mu | s1(60-63)
        op[j2] = expf(a2);                         // s1/s2
        if (j3 < NO) {
            float o3;
            if (j3 < 100)      o3 = expf(a3);      // s2
            else if (j3 < 120) o3 = tanhf(a3);     // rho
            else               o3 = sigf(a3);      // eos
            op[j3] = o3;
        }
    }
}

// =====================================================================
// launch
// =====================================================================
extern "C" void kernel_launch(void* const* d_in, const int* in_sizes, int n_in,
                              void* d_out, int out_size)
{
    const float* strokes = (const float*)d_in[0];
    const int*   chars   = (const int*)  d_in[1];
    const int*   lens    = (const int*)  d_in[2];
    const float* Wx0 = (const float*)d_in[3];
    const float* Wh0 = (const float*)d_in[4];
    const float* b0  = (const float*)d_in[5];
    const float* p0  = (const float*)d_in[6];
    const float* Wx1 = (const float*)d_in[7];
    const float* Wh1 = (const float*)d_in[8];
    const float* b1  = (const float*)d_in[9];
    const float* p1  = (const float*)d_in[10];
    const float* Wx2 = (const float*)d_in[11];
    const float* Wh2 = (const float*)d_in[12];
    const float* b2  = (const float*)d_in[13];
    const float* p2  = (const float*)d_in[14];
    const float* Watt = (const float*)d_in[15];
    const float* batt = (const float*)d_in[16];
    const float* Wmdn = (const float*)d_in[17];
    const float* bmdn = (const float*)d_in[18];
    float* out = (float*)d_out;

    static int smem_set = 0;
    if (!smem_set) {
        cudaFuncSetAttribute(rnn_kernel, cudaFuncAttributeMaxDynamicSharedMemorySize, SMEM_BYTES);
        smem_set = 1;
    }

    pack_kernel<<<256, 256>>>(Wx0, Wh0, Wx1, Wh1, Wx2, Wh2);
    rnn_kernel<<<NCTA, NTH, SMEM_BYTES>>>(strokes, chars, lens,
                                          b0, p0, b1, p1, b2, p2,
                                          Watt, batt, Wmdn, bmdn, out);
}